// round 6
// baseline (speedup 1.0000x reference)
#include <cuda_runtime.h>
#include <cuda_bf16.h>
#include <math.h>
#include <stdint.h>

#define BB 16
#define NN 1024
#define CC 768
#define NH 12
#define HD 64
#define ROWS (BB*NN)        // 16384

// GEMM tiling (mma.sync + cp.async path)
#define BM 128
#define BN 128
#define BK 32               // k elements per chunk
#define PITCH 40            // smem row pitch (bf16): 80B rows, 16B-aligned, conflict-free
#define NSTAGE 3
#define PLANE_ELEMS (128*PITCH)                 // 5120
#define GEMM_SMEM (NSTAGE*4*PLANE_ELEMS*2)      // 122880 B
#define GTHREADS 512

// ---------------- device scratch ----------------
__device__ float g_qkv[ROWS*3*CC];      // qkv projections fp32
__device__ float g_eta[BB*NH*NN];
__device__ float g_x2[ROWS*CC];         // x after proj residual (fp32)
__device__ float g_qkvbias[3*CC];
__device__ __align__(16) __nv_bfloat16 g_hhi[ROWS*CC],    g_hlo[ROWS*CC];     // h / h2 planes
__device__ __align__(16) __nv_bfloat16 g_attnhi[ROWS*CC], g_attnlo[ROWS*CC];
__device__ __align__(16) __nv_bfloat16 g_acthi[ROWS*4*CC], g_actlo[ROWS*4*CC];
__device__ __align__(16) __nv_bfloat16 g_wqhi[3*CC*CC],  g_wqlo[3*CC*CC];
__device__ __align__(16) __nv_bfloat16 g_wphi[CC*CC],    g_wplo[CC*CC];
__device__ __align__(16) __nv_bfloat16 g_w1hi[4*CC*CC],  g_w1lo[4*CC*CC];
__device__ __align__(16) __nv_bfloat16 g_w2hi[CC*4*CC],  g_w2lo[CC*4*CC];

// ---------------- helpers ----------------
__device__ __forceinline__ float warpsum(float v) {
#pragma unroll
    for (int o = 16; o > 0; o >>= 1) v += __shfl_xor_sync(0xffffffffu, v, o);
    return v;
}
__device__ __forceinline__ void split2(float v, __nv_bfloat16& hi, __nv_bfloat16& lo) {
    hi = __float2bfloat16(v);
    lo = __float2bfloat16(v - __bfloat162float(hi));
}
__device__ __forceinline__ void mma16816(float* d, const uint32_t* a, const uint32_t* b) {
    asm volatile(
        "mma.sync.aligned.m16n8k16.row.col.f32.bf16.bf16.f32 "
        "{%0,%1,%2,%3}, {%4,%5,%6,%7}, {%8,%9}, {%0,%1,%2,%3};"
        : "+f"(d[0]), "+f"(d[1]), "+f"(d[2]), "+f"(d[3])
        : "r"(a[0]), "r"(a[1]), "r"(a[2]), "r"(a[3]), "r"(b[0]), "r"(b[1]));
}
__device__ __forceinline__ void cpasync16(uint32_t dst, const void* src) {
    asm volatile("cp.async.cg.shared.global [%0], [%1], 16;" :: "r"(dst), "l"(src));
}
__device__ __forceinline__ uint32_t smaddr(const void* p) {
    uint32_t a;
    asm("{ .reg .u64 t; cvta.to.shared.u64 t, %1; cvt.u32.u64 %0, t; }" : "=r"(a) : "l"(p));
    return a;
}
__device__ __forceinline__ void ldm_x4(uint32_t* r, uint32_t addr) {
    asm volatile("ldmatrix.sync.aligned.m8n8.x4.shared.b16 {%0,%1,%2,%3}, [%4];"
        : "=r"(r[0]), "=r"(r[1]), "=r"(r[2]), "=r"(r[3]) : "r"(addr));
}

// ---------------- small elementwise kernels ----------------
__global__ void qkvbias_kernel(const float* __restrict__ qb,
                               const float* __restrict__ vb,
                               float* __restrict__ out) {
    int i = blockIdx.x * blockDim.x + threadIdx.x;
    if (i < 3*CC) out[i] = (i < CC) ? qb[i] : (i < 2*CC ? 0.0f : vb[i - 2*CC]);
}
__global__ void convert_split(const float* __restrict__ in,
                              __nv_bfloat16* __restrict__ hi,
                              __nv_bfloat16* __restrict__ lo, int n) {
    int i = blockIdx.x * blockDim.x + threadIdx.x;
    if (i < n) { __nv_bfloat16 h, l; split2(in[i], h, l); hi[i] = h; lo[i] = l; }
}

// ---------------- LayerNorm (+ optional eta), split planes out ----------------
__global__ void __launch_bounds__(256) ln_kernel(
    const float* __restrict__ x, const float* __restrict__ w, const float* __restrict__ bp,
    const float* __restrict__ lrw, const float* __restrict__ lrb,
    __nv_bfloat16* __restrict__ hhi, __nv_bfloat16* __restrict__ hlo,
    float* __restrict__ eta)
{
    __shared__ float redA[8], redB[8], pr[8*NH];
    int row = blockIdx.x;
    int tid = threadIdx.x, lane = tid & 31, warp = tid >> 5;
    const float* xr = x + (size_t)row * CC;
    float v0 = xr[tid], v1 = xr[tid+256], v2 = xr[tid+512];

    float s = warpsum(v0+v1+v2);
    if (lane == 0) redA[warp] = s;
    __syncthreads();
    float tot = 0.f;
#pragma unroll
    for (int i = 0; i < 8; i++) tot += redA[i];
    float mu = tot * (1.0f/CC);
    float d0 = v0-mu, d1 = v1-mu, d2 = v2-mu;
    float vsum = warpsum(d0*d0 + d1*d1 + d2*d2);
    if (lane == 0) redB[warp] = vsum;
    __syncthreads();
    float var = 0.f;
#pragma unroll
    for (int i = 0; i < 8; i++) var += redB[i];
    var *= (1.0f/CC);
    float rstd = rsqrtf(var + 1e-6f);

    float h0 = w[tid    ]*d0*rstd + bp[tid    ];
    float h1 = w[tid+256]*d1*rstd + bp[tid+256];
    float h2 = w[tid+512]*d2*rstd + bp[tid+512];
    size_t rb = (size_t)row * CC;
    __nv_bfloat16 hh, hl;
    split2(h0, hh, hl); hhi[rb+tid]     = hh; hlo[rb+tid]     = hl;
    split2(h1, hh, hl); hhi[rb+tid+256] = hh; hlo[rb+tid+256] = hl;
    split2(h2, hh, hl); hhi[rb+tid+512] = hh; hlo[rb+tid+512] = hl;

    if (eta) {
        float p[NH];
#pragma unroll
        for (int hh2 = 0; hh2 < NH; hh2++) {
            const float* lw = lrw + (size_t)hh2 * CC;
            p[hh2] = h0*lw[tid] + h1*lw[tid+256] + h2*lw[tid+512];
        }
#pragma unroll
        for (int hh2 = 0; hh2 < NH; hh2++) {
            float ps = warpsum(p[hh2]);
            if (lane == 0) pr[warp*NH + hh2] = ps;
        }
        __syncthreads();
        if (tid < NH) {
            float ss = 0.f;
#pragma unroll
            for (int wv = 0; wv < 8; wv++) ss += pr[wv*NH + tid];
            ss += lrb[tid];
            float sg = 1.0f / (1.0f + expf(-ss));
            int b = row >> 10, n = row & 1023;
            eta[((size_t)(b*NH + tid))*NN + n] = sg * (1.0f/HD);
        }
    }
}

// ---------------- cp.async + ldmatrix pipelined split-bf16 GEMM NT ----------------
// 512 threads, 16 warps in 4x4 grid, warp tile 32x32
// EPI: 0 = fp32 out; 1 = +Res fp32 out; 2 = gelu, split planes out
template<int EPI>
__global__ void __launch_bounds__(GTHREADS, 1) gemm_mma(
    const __nv_bfloat16* __restrict__ Ahi, const __nv_bfloat16* __restrict__ Alo,
    const __nv_bfloat16* __restrict__ Bhi, const __nv_bfloat16* __restrict__ Blo,
    const float* __restrict__ bias, const float* __restrict__ Res,
    float* __restrict__ Cout,
    __nv_bfloat16* __restrict__ Chi, __nv_bfloat16* __restrict__ Clo,
    int M, int Nn, int K)
{
    extern __shared__ __nv_bfloat16 smem[];
    uint32_t smbase = smaddr(smem);

    int tid = threadIdx.x;
    int lane = tid & 31, wid = tid >> 5;
    int wm = wid & 3, wn = wid >> 2;          // 4x4 warp grid, warp tile 32x32
    int g = lane >> 2, t4 = lane & 3;
    int bn = blockIdx.x * BN, bm = blockIdx.y * BM;
    const int nch = K / BK;

    const __nv_bfloat16* planes[4] = {
        Ahi + (size_t)bm*K, Alo + (size_t)bm*K,
        Bhi + (size_t)bn*K, Blo + (size_t)bn*K };

    // cp.async coords: per plane, 128 rows x 4 segs of 16B = 512 tasks = 512 threads
    int lrow = tid >> 2, lseg = tid & 3;

    // ldmatrix lane row offsets (element units), add kof and tile offsets per use
    int aRow = (wm*32 + (lane & 15))*PITCH + (lane >> 4)*8;
    int bRow = (wn*32 + (lane >> 4)*8 + (lane & 7))*PITCH + ((lane >> 3) & 1)*8;

    float acc[2][4][4];
#pragma unroll
    for (int i = 0; i < 2; i++)
#pragma unroll
        for (int j = 0; j < 4; j++)
#pragma unroll
            for (int k = 0; k < 4; k++) acc[i][j][k] = 0.f;

#define ISSUE(stage, c) do {                                                    \
        int kb = (c) * BK;                                                      \
        _Pragma("unroll")                                                       \
        for (int p = 0; p < 4; p++) {                                           \
            uint32_t dst = smbase +                                             \
                (((stage)*4 + p)*PLANE_ELEMS + lrow*PITCH + lseg*8)*2;          \
            cpasync16(dst, planes[p] + (size_t)lrow*K + kb + lseg*8);           \
        }                                                                       \
        asm volatile("cp.async.commit_group;" ::: "memory");                    \
    } while (0)

    ISSUE(0, 0);
    ISSUE(1, 1);

    for (int c = 0; c < nch; ++c) {
        int s = c % NSTAGE;
        asm volatile("cp.async.wait_group %0;" :: "n"(NSTAGE-2) : "memory");
        __syncthreads();
        int cn = c + NSTAGE - 1;
        if (cn < nch) ISSUE(cn % NSTAGE, cn);

        uint32_t pAhi = smbase + ((s*4 + 0)*PLANE_ELEMS)*2;
        uint32_t pAlo = smbase + ((s*4 + 1)*PLANE_ELEMS)*2;
        uint32_t pBhi = smbase + ((s*4 + 2)*PLANE_ELEMS)*2;
        uint32_t pBlo = smbase + ((s*4 + 3)*PLANE_ELEMS)*2;

#pragma unroll
        for (int ks = 0; ks < 2; ks++) {
            int kof = ks*16;
            uint32_t ah[2][4], al[2][4], bh[4][2], bl[4][2];
#pragma unroll
            for (int mb = 0; mb < 2; mb++) {
                ldm_x4(ah[mb], pAhi + (aRow + mb*16*PITCH + kof)*2);
                ldm_x4(al[mb], pAlo + (aRow + mb*16*PITCH + kof)*2);
            }
#pragma unroll
            for (int p = 0; p < 2; p++) {
                uint32_t r[4];
                ldm_x4(r, pBhi + (bRow + p*16*PITCH + kof)*2);
                bh[2*p][0] = r[0]; bh[2*p][1] = r[1]; bh[2*p+1][0] = r[2]; bh[2*p+1][1] = r[3];
                ldm_x4(r, pBlo + (bRow + p*16*PITCH + kof)*2);
                bl[2*p][0] = r[0]; bl[2*p][1] = r[1]; bl[2*p+1][0] = r[2]; bl[2*p+1][1] = r[3];
            }
            // term-major: RAW distance 8 on each accumulator
#pragma unroll
            for (int mt = 0; mt < 2; mt++)
#pragma unroll
                for (int nt = 0; nt < 4; nt++) mma16816(acc[mt][nt], ah[mt], bh[nt]);
#pragma unroll
            for (int mt = 0; mt < 2; mt++)
#pragma unroll
                for (int nt = 0; nt < 4; nt++) mma16816(acc[mt][nt], ah[mt], bl[nt]);
#pragma unroll
            for (int mt = 0; mt < 2; mt++)
#pragma unroll
                for (int nt = 0; nt < 4; nt++) mma16816(acc[mt][nt], al[mt], bh[nt]);
        }
    }
#undef ISSUE

    // epilogue: direct register -> global
#pragma unroll
    for (int mt = 0; mt < 2; mt++) {
#pragma unroll
        for (int nt = 0; nt < 4; nt++) {
            int r0 = bm + wm*32 + mt*16 + g;
            int c0 = bn + wn*32 + nt*8 + t4*2;
            float b0 = bias[c0], b1 = bias[c0+1];
#pragma unroll
            for (int half = 0; half < 2; half++) {
                int r = r0 + half*8;
                size_t gi = (size_t)r * Nn + c0;
                float v0 = acc[mt][nt][half*2]     + b0;
                float v1 = acc[mt][nt][half*2 + 1] + b1;
                if (EPI == 1) { v0 += Res[gi]; v1 += Res[gi+1]; }
                if (EPI == 2) {
                    v0 = 0.5f*v0*(1.0f + erff(v0*0.70710678118654752f));
                    v1 = 0.5f*v1*(1.0f + erff(v1*0.70710678118654752f));
                    __nv_bfloat16 hh, hl;
                    split2(v0, hh, hl); Chi[gi]   = hh; Clo[gi]   = hl;
                    split2(v1, hh, hl); Chi[gi+1] = hh; Clo[gi+1] = hl;
                } else {
                    Cout[gi]   = v0;
                    Cout[gi+1] = v1;
                }
            }
        }
    }
}

// ---------------- TTT kernel: one block per (b,h) ----------------
__global__ void __launch_bounds__(256) ttt_kernel(
    const float* __restrict__ qkv, const float* __restrict__ eta,
    const float* __restrict__ W1g, const float* __restrict__ b1g,
    const float* __restrict__ tttw, const float* __restrict__ tttb,
    __nv_bfloat16* __restrict__ attnhi, __nv_bfloat16* __restrict__ attnlo)
{
    extern __shared__ float sm[];
    float* sW1  = sm;            // 4096 (becomes W1_bar)
    float* sK   = sm + 4096;
    float* sV   = sm + 8192;
    float* sZ   = sm + 12288;
    float* sEta = sm + 16384;    // 64
    float* sGw  = sEta + 64;
    float* sGb  = sGw + 64;
    float* sB1  = sGb + 64;
    float* sB1b = sB1 + 64;
    float* sBred= sB1b + 64;     // 256

    int bh = blockIdx.x;
    int b = bh / NH, h = bh % NH;
    int tid = threadIdx.x, tx = tid & 63, ty = tid >> 6;
    int lane = tid & 31, warp = tid >> 5;

    for (int i = tid; i < 4096; i += 256) sW1[i] = W1g[h*4096 + i];
    if (tid < 64) {
        sGw[tid] = tttw[h*64 + tid];
        sGb[tid] = tttb[h*64 + tid];
        sB1[tid] = b1g[h*64 + tid];
    }
    __syncthreads();

    const size_t rs = 3*CC;
    const float* qbase = qkv + (size_t)b*NN*rs + 0*CC + h*HD;
    const float* kbase = qkv + (size_t)b*NN*rs + 1*CC + h*HD;
    const float* vbase = qkv + (size_t)b*NN*rs + 2*CC + h*HD;

    float accW[16];
#pragma unroll
    for (int i = 0; i < 16; i++) accW[i] = 0.f;
    float accB = 0.f;

    for (int c = 0; c < 16; c++) {
        int n0 = c * 64;
        for (int i = tid; i < 4096; i += 256) {
            int n = i >> 6, e = i & 63;
            sK[i] = kbase[(size_t)(n0+n)*rs + e];
            sV[i] = vbase[(size_t)(n0+n)*rs + e];
        }
        if (tid < 64) sEta[tid] = eta[(size_t)bh*NN + n0 + tid];
        __syncthreads();

        {
            float az[16];
#pragma unroll
            for (int i = 0; i < 16; i++) az[i] = sB1[tx];
            for (int d = 0; d < 64; d++) {
                float w = sW1[d*64 + tx];
#pragma unroll
                for (int i = 0; i < 16; i++) az[i] += sK[(i*4 + ty)*64 + d] * w;
            }
#pragma unroll
            for (int i = 0; i < 16; i++) sZ[(i*4 + ty)*64 + tx] = az[i];
        }
        __syncthreads();

        for (int j = 0; j < 8; j++) {
            int n = warp + 8*j;
            float z0 = sZ[n*64 + lane], z1 = sZ[n*64 + lane + 32];
            float mu = warpsum(z0 + z1) * (1.0f/64);
            float d0 = z0 - mu, d1 = z1 - mu;
            float var = warpsum(d0*d0 + d1*d1) * (1.0f/64);
            float rstd = rsqrtf(var + 1e-6f);
            float xh0 = d0*rstd, xh1 = d1*rstd;
            float t0 = sV[n*64 + lane]      - sK[n*64 + lane];
            float t1 = sV[n*64 + lane + 32] - sK[n*64 + lane + 32];
            float g0 = sGw[lane], g1 = sGw[lane + 32];
            float gho0 = (g0*xh0 + sGb[lane]      - t0) * g0;
            float gho1 = (g1*xh1 + sGb[lane + 32] - t1) * g1;
            float sg  = warpsum(gho0 + gho1);
            float sgx = warpsum(gho0*xh0 + gho1*xh1);
            float e = sEta[n];
            float inv = rstd * (1.0f/64) * e;
            sZ[n*64 + lane]      = (64.f*gho0 - sg - xh0*sgx) * inv;
            sZ[n*64 + lane + 32] = (64.f*gho1 - sg - xh1*sgx) * inv;
        }
        __syncthreads();

        for (int n = 0; n < 64; n++) {
            float z = sZ[n*64 + tx];
            const float* kr = &sK[n*64 + ty*16];
#pragma unroll
            for (int i = 0; i < 16; i++) accW[i] += kr[i] * z;
            if ((n >> 4) == ty) accB += z;
        }
        __syncthreads();
    }

#pragma unroll
    for (int i = 0; i < 16; i++) sW1[(ty*16 + i)*64 + tx] -= accW[i];
    sBred[ty*64 + tx] = accB;
    __syncthreads();
    if (ty == 0)
        sB1b[tx] = sB1[tx] - (sBred[tx] + sBred[64+tx] + sBred[128+tx] + sBred[192+tx]);
    __syncthreads();

    for (int c = 0; c < 16; c++) {
        int n0 = c * 64;
        for (int i = tid; i < 4096; i += 256) {
            int n = i >> 6, e = i & 63;
            sK[i] = qbase[(size_t)(n0+n)*rs + e];
        }
        __syncthreads();
        {
            float az[16];
#pragma unroll
            for (int i = 0; i < 16; i++) az[i] = sB1b[tx];
            for (int d = 0; d < 64; d++) {
                float w = sW1[d*64 + tx];
#pragma unroll
                for (int i = 0; i < 16; i++) az[i] += sK[(i*4 + ty)*64 + d] * w;
            }
#pragma unroll
            for (int i = 0; i < 16; i++) sZ[(i*4 + ty)*64 + tx] = az[i];
        }
        __syncthreads();
        for (int j = 0; j < 8; j++) {
            int n = warp + 8*j;
            float z0 = sZ[n*64 + lane], z1 = sZ[n*64 + lane + 32];
            float mu = warpsum(z0 + z1) * (1.0f/64);
            float d0 = z0 - mu, d1 = z1 - mu;
            float var = warpsum(d0*d0 + d1*d1) * (1.0f/64);
            float rstd = rsqrtf(var + 1e-6f);
            float o0 = sK[n*64 + lane]      + sGw[lane]     *d0*rstd + sGb[lane];
            float o1 = sK[n*64 + lane + 32] + sGw[lane + 32]*d1*rstd + sGb[lane + 32];
            size_t orow = ((size_t)(b*NN + n0 + n))*CC + h*HD;
            __nv_bfloat16 hh, hl;
            split2(o0, hh, hl); attnhi[orow + lane]      = hh; attnlo[orow + lane]      = hl;
            split2(o1, hh, hl); attnhi[orow + lane + 32] = hh; attnlo[orow + lane + 32] = hl;
        }
        __syncthreads();
    }
}

// ---------------- launch ----------------
extern "C" void kernel_launch(void* const* d_in, const int* in_sizes, int n_in,
                              void* d_out, int out_size) {
    const float* x      = (const float*)d_in[0];
    const float* qkv_w  = (const float*)d_in[1];
    const float* q_bias = (const float*)d_in[2];
    const float* v_bias = (const float*)d_in[3];
    const float* proj_w = (const float*)d_in[4];
    const float* proj_b = (const float*)d_in[5];
    const float* lr_w   = (const float*)d_in[6];
    const float* lr_b   = (const float*)d_in[7];
    const float* W1     = (const float*)d_in[8];
    const float* b1     = (const float*)d_in[9];
    const float* ttt_w  = (const float*)d_in[10];
    const float* ttt_b  = (const float*)d_in[11];
    const float* n1w    = (const float*)d_in[12];
    const float* n1b    = (const float*)d_in[13];
    const float* n2w    = (const float*)d_in[14];
    const float* n2b    = (const float*)d_in[15];
    const float* fc1_w  = (const float*)d_in[16];
    const float* fc1_b  = (const float*)d_in[17];
    const float* fc2_w  = (const float*)d_in[18];
    const float* fc2_b  = (const float*)d_in[19];
    float* out = (float*)d_out;

    float *qkvb, *etap, *x2, *qbias;
    __nv_bfloat16 *hhi, *hlo, *athi, *atlo, *achi, *aclo;
    __nv_bfloat16 *wqhi, *wqlo, *wphi, *wplo, *w1hi, *w1lo, *w2hi, *w2lo;
    cudaGetSymbolAddress((void**)&qkvb,  g_qkv);
    cudaGetSymbolAddress((void**)&etap,  g_eta);
    cudaGetSymbolAddress((void**)&x2,    g_x2);
    cudaGetSymbolAddress((void**)&qbias, g_qkvbias);
    cudaGetSymbolAddress((void**)&hhi,   g_hhi);
    cudaGetSymbolAddress((void**)&hlo,   g_hlo);
    cudaGetSymbolAddress((void**)&athi,  g_attnhi);
    cudaGetSymbolAddress((void**)&atlo,  g_attnlo);
    cudaGetSymbolAddress((void**)&achi,  g_acthi);
    cudaGetSymbolAddress((void**)&aclo,  g_actlo);
    cudaGetSymbolAddress((void**)&wqhi,  g_wqhi);
    cudaGetSymbolAddress((void**)&wqlo,  g_wqlo);
    cudaGetSymbolAddress((void**)&wphi,  g_wphi);
    cudaGetSymbolAddress((void**)&wplo,  g_wplo);
    cudaGetSymbolAddress((void**)&w1hi,  g_w1hi);
    cudaGetSymbolAddress((void**)&w1lo,  g_w1lo);
    cudaGetSymbolAddress((void**)&w2hi,  g_w2hi);
    cudaGetSymbolAddress((void**)&w2lo,  g_w2lo);

    const int TTT_SMEM = (16384 + 64*5 + 256) * 4;
    cudaFuncSetAttribute(ttt_kernel, cudaFuncAttributeMaxDynamicSharedMemorySize, TTT_SMEM);
    cudaFuncSetAttribute(gemm_mma<0>, cudaFuncAttributeMaxDynamicSharedMemorySize, GEMM_SMEM);
    cudaFuncSetAttribute(gemm_mma<1>, cudaFuncAttributeMaxDynamicSharedMemorySize, GEMM_SMEM);
    cudaFuncSetAttribute(gemm_mma<2>, cudaFuncAttributeMaxDynamicSharedMemorySize, GEMM_SMEM);

    // weight conversions (fp32 -> hi/lo planes)
    convert_split<<<(3*CC*CC + 255)/256, 256>>>(qkv_w, wqhi, wqlo, 3*CC*CC);
    convert_split<<<(CC*CC   + 255)/256, 256>>>(proj_w, wphi, wplo, CC*CC);
    convert_split<<<(4*CC*CC + 255)/256, 256>>>(fc1_w, w1hi, w1lo, 4*CC*CC);
    convert_split<<<(CC*4*CC + 255)/256, 256>>>(fc2_w, w2hi, w2lo, CC*4*CC);
    qkvbias_kernel<<<(3*CC + 255)/256, 256>>>(q_bias, v_bias, qbias);

    // LN1 + eta
    ln_kernel<<<ROWS, 256>>>(x, n1w, n1b, lr_w, lr_b, hhi, hlo, etap);
    // qkv = h @ qkv_w^T + qkvbias  (fp32 out for TTT)
    gemm_mma<0><<<dim3(3*CC/BN, ROWS/BM), GTHREADS, GEMM_SMEM>>>(
        hhi, hlo, wqhi, wqlo, qbias, nullptr, qkvb, nullptr, nullptr, ROWS, 3*CC, CC);
    // TTT attention
    ttt_kernel<<<BB*NH, 256, TTT_SMEM>>>(qkvb, etap, W1, b1, ttt_w, ttt_b, athi, atlo);
    // x2 = x + attn @ proj_w^T + proj_b
    gemm_mma<1><<<dim3(CC/BN, ROWS/BM), GTHREADS, GEMM_SMEM>>>(
        athi, atlo, wphi, wplo, proj_b, x, x2, nullptr, nullptr, ROWS, CC, CC);
    // LN2
    ln_kernel<<<ROWS, 256>>>(x2, n2w, n2b, nullptr, nullptr, hhi, hlo, nullptr);
    // act = gelu(h2 @ fc1_w^T + fc1_b), split planes
    gemm_mma<2><<<dim3(4*CC/BN, ROWS/BM), GTHREADS, GEMM_SMEM>>>(
        hhi, hlo, w1hi, w1lo, fc1_b, nullptr, nullptr, achi, aclo, ROWS, 4*CC, CC);
    // out = x2 + act @ fc2_w^T + fc2_b
    gemm_mma<1><<<dim3(CC/BN, ROWS/BM), GTHREADS, GEMM_SMEM>>>(
        achi, aclo, w2hi, w2lo, fc2_b, x2, out, nullptr, nullptr, ROWS, CC, 4*CC);
}

// round 8
// speedup vs baseline: 1.5062x; 1.5062x over previous
#include <cuda_runtime.h>
#include <cuda_fp16.h>
#include <math.h>
#include <stdint.h>

#define BB 16
#define NN 1024
#define CC 768
#define NH 12
#define HD 64
#define ROWS (BB*NN)        // 16384

// GEMM tiling (mma.sync + cp.async path)
#define BM 128
#define BN 128
#define BK 32               // k elements per chunk
#define PITCH 40            // smem row pitch (fp16): 80B rows, 16B-aligned, conflict-free
#define NSTAGE 3
#define PLANE_ELEMS (128*PITCH)                 // 5120
#define GEMM_SMEM (NSTAGE*3*PLANE_ELEMS*2)      // 92160 B -> 2 CTA/SM possible
#define GTHREADS 512

// ---------------- device scratch ----------------
__device__ float g_qkv[ROWS*3*CC];      // qkv projections fp32
__device__ float g_eta[BB*NH*NN];
__device__ float g_x2[ROWS*CC];         // x after proj residual (fp32)
__device__ float g_qkvbias[3*CC];
__device__ __align__(16) __half g_hhi[ROWS*CC],    g_hlo[ROWS*CC];     // h / h2 planes
__device__ __align__(16) __half g_attnhi[ROWS*CC], g_attnlo[ROWS*CC];
__device__ __align__(16) __half g_acthi[ROWS*4*CC], g_actlo[ROWS*4*CC];
__device__ __align__(16) __half g_wq[3*CC*CC];     // weights: single fp16 plane
__device__ __align__(16) __half g_wp[CC*CC];
__device__ __align__(16) __half g_w1[4*CC*CC];
__device__ __align__(16) __half g_w2[CC*4*CC];

// ---------------- helpers ----------------
__device__ __forceinline__ float warpsum(float v) {
#pragma unroll
    for (int o = 16; o > 0; o >>= 1) v += __shfl_xor_sync(0xffffffffu, v, o);
    return v;
}
__device__ __forceinline__ void split2h(float v, __half& hi, __half& lo) {
    hi = __float2half_rn(v);
    lo = __float2half_rn(v - __half2float(hi));
}
__device__ __forceinline__ void mma16816(float* d, const uint32_t* a, const uint32_t* b) {
    asm volatile(
        "mma.sync.aligned.m16n8k16.row.col.f32.f16.f16.f32 "
        "{%0,%1,%2,%3}, {%4,%5,%6,%7}, {%8,%9}, {%0,%1,%2,%3};"
        : "+f"(d[0]), "+f"(d[1]), "+f"(d[2]), "+f"(d[3])
        : "r"(a[0]), "r"(a[1]), "r"(a[2]), "r"(a[3]), "r"(b[0]), "r"(b[1]));
}
__device__ __forceinline__ void cpasync16(uint32_t dst, const void* src) {
    asm volatile("cp.async.cg.shared.global [%0], [%1], 16;" :: "r"(dst), "l"(src));
}
__device__ __forceinline__ uint32_t smaddr(const void* p) {
    uint32_t a;
    asm("{ .reg .u64 t; cvta.to.shared.u64 t, %1; cvt.u32.u64 %0, t; }" : "=r"(a) : "l"(p));
    return a;
}
__device__ __forceinline__ void ldm_x4(uint32_t* r, uint32_t addr) {
    asm volatile("ldmatrix.sync.aligned.m8n8.x4.shared.b16 {%0,%1,%2,%3}, [%4];"
        : "=r"(r[0]), "=r"(r[1]), "=r"(r[2]), "=r"(r[3]) : "r"(addr));
}

// ---------------- small elementwise kernels ----------------
__global__ void qkvbias_kernel(const float* __restrict__ qb,
                               const float* __restrict__ vb,
                               float* __restrict__ out) {
    int i = blockIdx.x * blockDim.x + threadIdx.x;
    if (i < 3*CC) out[i] = (i < CC) ? qb[i] : (i < 2*CC ? 0.0f : vb[i - 2*CC]);
}
// one merged weight-conversion kernel: fp32 -> fp16
#define WQ_N (3*CC*CC)
#define WP_N (CC*CC)
#define W1_N (4*CC*CC)
#define W2_N (CC*4*CC)
__global__ void convert_w(const float* __restrict__ qkv_w, const float* __restrict__ proj_w,
                          const float* __restrict__ fc1_w, const float* __restrict__ fc2_w,
                          __half* __restrict__ wq, __half* __restrict__ wp,
                          __half* __restrict__ w1, __half* __restrict__ w2) {
    int i = blockIdx.x * blockDim.x + threadIdx.x;
    if (i < WQ_N) wq[i] = __float2half_rn(qkv_w[i]);
    else if (i < WQ_N + WP_N) { int j = i - WQ_N; wp[j] = __float2half_rn(proj_w[j]); }
    else if (i < WQ_N + WP_N + W1_N) { int j = i - WQ_N - WP_N; w1[j] = __float2half_rn(fc1_w[j]); }
    else if (i < WQ_N + WP_N + W1_N + W2_N) { int j = i - WQ_N - WP_N - W1_N; w2[j] = __float2half_rn(fc2_w[j]); }
}

// ---------------- LayerNorm (+ optional eta), split fp16 planes out ----------------
__global__ void __launch_bounds__(256) ln_kernel(
    const float* __restrict__ x, const float* __restrict__ w, const float* __restrict__ bp,
    const float* __restrict__ lrw, const float* __restrict__ lrb,
    __half* __restrict__ hhi, __half* __restrict__ hlo,
    float* __restrict__ eta)
{
    __shared__ float redA[8], redB[8], pr[8*NH];
    int row = blockIdx.x;
    int tid = threadIdx.x, lane = tid & 31, warp = tid >> 5;
    const float* xr = x + (size_t)row * CC;
    float v0 = xr[tid], v1 = xr[tid+256], v2 = xr[tid+512];

    float s = warpsum(v0+v1+v2);
    if (lane == 0) redA[warp] = s;
    __syncthreads();
    float tot = 0.f;
#pragma unroll
    for (int i = 0; i < 8; i++) tot += redA[i];
    float mu = tot * (1.0f/CC);
    float d0 = v0-mu, d1 = v1-mu, d2 = v2-mu;
    float vsum = warpsum(d0*d0 + d1*d1 + d2*d2);
    if (lane == 0) redB[warp] = vsum;
    __syncthreads();
    float var = 0.f;
#pragma unroll
    for (int i = 0; i < 8; i++) var += redB[i];
    var *= (1.0f/CC);
    float rstd = rsqrtf(var + 1e-6f);

    float h0 = w[tid    ]*d0*rstd + bp[tid    ];
    float h1 = w[tid+256]*d1*rstd + bp[tid+256];
    float h2 = w[tid+512]*d2*rstd + bp[tid+512];
    size_t rb = (size_t)row * CC;
    __half hh, hl;
    split2h(h0, hh, hl); hhi[rb+tid]     = hh; hlo[rb+tid]     = hl;
    split2h(h1, hh, hl); hhi[rb+tid+256] = hh; hlo[rb+tid+256] = hl;
    split2h(h2, hh, hl); hhi[rb+tid+512] = hh; hlo[rb+tid+512] = hl;

    if (eta) {
        float p[NH];
#pragma unroll
        for (int hh2 = 0; hh2 < NH; hh2++) {
            const float* lw = lrw + (size_t)hh2 * CC;
            p[hh2] = h0*lw[tid] + h1*lw[tid+256] + h2*lw[tid+512];
        }
#pragma unroll
        for (int hh2 = 0; hh2 < NH; hh2++) {
            float ps = warpsum(p[hh2]);
            if (lane == 0) pr[warp*NH + hh2] = ps;
        }
        __syncthreads();
        if (tid < NH) {
            float ss = 0.f;
#pragma unroll
            for (int wv = 0; wv < 8; wv++) ss += pr[wv*NH + tid];
            ss += lrb[tid];
            float sg = 1.0f / (1.0f + expf(-ss));
            int b = row >> 10, n = row & 1023;
            eta[((size_t)(b*NH + tid))*NN + n] = sg * (1.0f/HD);
        }
    }
}

// ---------------- cp.async + ldmatrix pipelined 2-term fp16 GEMM NT ----------------
// C[M,Nn] = epi((Ahi+Alo) @ Bf16^T + bias); A exact fp16 pair, B single fp16 plane
// 512 threads, 16 warps in 4x4 grid, warp tile 32x32
// EPI: 0 = fp32 out; 1 = +Res fp32 out; 2 = gelu, split fp16 planes out
template<int EPI>
__global__ void __launch_bounds__(GTHREADS, 2) gemm_mma(
    const __half* __restrict__ Ahi, const __half* __restrict__ Alo,
    const __half* __restrict__ Bw,
    const float* __restrict__ bias, const float* __restrict__ Res,
    float* __restrict__ Cout,
    __half* __restrict__ Chi, __half* __restrict__ Clo,
    int M, int Nn, int K)
{
    extern __shared__ __half smem[];
    uint32_t smbase = smaddr(smem);

    int tid = threadIdx.x;
    int lane = tid & 31, wid = tid >> 5;
    int wm = wid & 3, wn = wid >> 2;          // 4x4 warp grid, warp tile 32x32
    int g = lane >> 2, t4 = lane & 3;
    int bn = blockIdx.x * BN, bm = blockIdx.y * BM;
    const int nch = K / BK;

    const __half* planes[3] = {
        Ahi + (size_t)bm*K, Alo + (size_t)bm*K, Bw + (size_t)bn*K };

    // cp.async coords: per plane, 128 rows x 4 segs of 16B = 512 tasks = 512 threads
    int lrow = tid >> 2, lseg = tid & 3;

    // ldmatrix lane row offsets (element units)
    int aRow = (wm*32 + (lane & 15))*PITCH + (lane >> 4)*8;
    int bRow = (wn*32 + (lane >> 4)*8 + (lane & 7))*PITCH + ((lane >> 3) & 1)*8;

    float acc[2][4][4];
#pragma unroll
    for (int i = 0; i < 2; i++)
#pragma unroll
        for (int j = 0; j < 4; j++)
#pragma unroll
            for (int k = 0; k < 4; k++) acc[i][j][k] = 0.f;

#define ISSUE(stage, c) do {                                                    \
        int kb = (c) * BK;                                                      \
        _Pragma("unroll")                                                       \
        for (int p = 0; p < 3; p++) {                                           \
            uint32_t dst = smbase +                                             \
                (((stage)*3 + p)*PLANE_ELEMS + lrow*PITCH + lseg*8)*2;          \
            cpasync16(dst, planes[p] + (size_t)lrow*K + kb + lseg*8);           \
        }                                                                       \
        asm volatile("cp.async.commit_group;" ::: "memory");                    \
    } while (0)

    ISSUE(0, 0);
    ISSUE(1, 1);

    for (int c = 0; c < nch; ++c) {
        int s = c % NSTAGE;
        asm volatile("cp.async.wait_group %0;" :: "n"(NSTAGE-2) : "memory");
        __syncthreads();
        int cn = c + NSTAGE - 1;
        if (cn < nch) ISSUE(cn % NSTAGE, cn);

        uint32_t pAhi = smbase + ((s*3 + 0)*PLANE_ELEMS)*2;
        uint32_t pAlo = smbase + ((s*3 + 1)*PLANE_ELEMS)*2;
        uint32_t pB   = smbase + ((s*3 + 2)*PLANE_ELEMS)*2;

#pragma unroll
        for (int ks = 0; ks < 2; ks++) {
            int kof = ks*16;
            uint32_t ah[2][4], al[2][4], bh[4][2];
#pragma unroll
            for (int mb = 0; mb < 2; mb++) {
                ldm_x4(ah[mb], pAhi + (aRow + mb*16*PITCH + kof)*2);
                ldm_x4(al[mb], pAlo + (aRow + mb*16*PITCH + kof)*2);
            }
#pragma unroll
            for (int p = 0; p < 2; p++) {
                uint32_t r[4];
                ldm_x4(r, pB + (bRow + p*16*PITCH + kof)*2);
                bh[2*p][0] = r[0]; bh[2*p][1] = r[1]; bh[2*p+1][0] = r[2]; bh[2*p+1][1] = r[3];
            }
            // term-major: RAW distance 8 on each accumulator
#pragma unroll
            for (int mt = 0; mt < 2; mt++)
#pragma unroll
                for (int nt = 0; nt < 4; nt++) mma16816(acc[mt][nt], ah[mt], bh[nt]);
#pragma unroll
            for (int mt = 0; mt < 2; mt++)
#pragma unroll
                for (int nt = 0; nt < 4; nt++) mma16816(acc[mt][nt], al[mt], bh[nt]);
        }
    }
#undef ISSUE

    // epilogue: direct register -> global
#pragma unroll
    for (int mt = 0; mt < 2; mt++) {
#pragma unroll
        for (int nt = 0; nt < 4; nt++) {
            int r0 = bm + wm*32 + mt*16 + g;
            int c0 = bn + wn*32 + nt*8 + t4*2;
            float b0 = bias[c0], b1 = bias[c0+1];
#pragma unroll
            for (int half = 0; half < 2; half++) {
                int r = r0 + half*8;
                size_t gi = (size_t)r * Nn + c0;
                float v0 = acc[mt][nt][half*2]     + b0;
                float v1 = acc[mt][nt][half*2 + 1] + b1;
                if (EPI == 1) { v0 += Res[gi]; v1 += Res[gi+1]; }
                if (EPI == 2) {
                    v0 = 0.5f*v0*(1.0f + erff(v0*0.70710678118654752f));
                    v1 = 0.5f*v1*(1.0f + erff(v1*0.70710678118654752f));
                    __half hh, hl;
                    split2h(v0, hh, hl); Chi[gi]   = hh; Clo[gi]   = hl;
                    split2h(v1, hh, hl); Chi[gi+1] = hh; Clo[gi+1] = hl;
                } else {
                    Cout[gi]   = v0;
                    Cout[gi+1] = v1;
                }
            }
        }
    }
}

// ---------------- TTT kernel: one block per (b,h) ----------------
__global__ void __launch_bounds__(256) ttt_kernel(
    const float* __restrict__ qkv, const float* __restrict__ eta,
    const float* __restrict__ W1g, const float* __restrict__ b1g,
    const float* __restrict__ tttw, const float* __restrict__ tttb,
    __half* __restrict__ attnhi, __half* __restrict__ attnlo)
{
    extern __shared__ float sm[];
    float* sW1  = sm;            // 4096 (becomes W1_bar)
    float* sK   = sm + 4096;
    float* sV   = sm + 8192;
    float* sZ   = sm + 12288;
    float* sEta = sm + 16384;    // 64
    float* sGw  = sEta + 64;
    float* sGb  = sGw + 64;
    float* sB1  = sGb + 64;
    float* sB1b = sB1 + 64;
    float* sBred= sB1b + 64;     // 256

    int bh = blockIdx.x;
    int b = bh / NH, h = bh % NH;
    int tid = threadIdx.x, tx = tid & 63, ty = tid >> 6;
    int lane = tid & 31, warp = tid >> 5;

    for (int i = tid; i < 4096; i += 256) sW1[i] = W1g[h*4096 + i];
    if (tid < 64) {
        sGw[tid] = tttw[h*64 + tid];
        sGb[tid] = tttb[h*64 + tid];
        sB1[tid] = b1g[h*64 + tid];
    }
    __syncthreads();

    const size_t rs = 3*CC;
    const float* qbase = qkv + (size_t)b*NN*rs + 0*CC + h*HD;
    const float* kbase = qkv + (size_t)b*NN*rs + 1*CC + h*HD;
    const float* vbase = qkv + (size_t)b*NN*rs + 2*CC + h*HD;

    float accW[16];
#pragma unroll
    for (int i = 0; i < 16; i++) accW[i] = 0.f;
    float accB = 0.f;

    for (int c = 0; c < 16; c++) {
        int n0 = c * 64;
        for (int i = tid; i < 4096; i += 256) {
            int n = i >> 6, e = i & 63;
            sK[i] = kbase[(size_t)(n0+n)*rs + e];
            sV[i] = vbase[(size_t)(n0+n)*rs + e];
        }
        if (tid < 64) sEta[tid] = eta[(size_t)bh*NN + n0 + tid];
        __syncthreads();

        {
            float az[16];
#pragma unroll
            for (int i = 0; i < 16; i++) az[i] = sB1[tx];
            for (int d = 0; d < 64; d++) {
                float w = sW1[d*64 + tx];
#pragma unroll
                for (int i = 0; i < 16; i++) az[i] += sK[(i*4 + ty)*64 + d] * w;
            }
#pragma unroll
            for (int i = 0; i < 16; i++) sZ[(i*4 + ty)*64 + tx] = az[i];
        }
        __syncthreads();

        for (int j = 0; j < 8; j++) {
            int n = warp + 8*j;
            float z0 = sZ[n*64 + lane], z1 = sZ[n*64 + lane + 32];
            float mu = warpsum(z0 + z1) * (1.0f/64);
            float d0 = z0 - mu, d1 = z1 - mu;
            float var = warpsum(d0*d0 + d1*d1) * (1.0f/64);
            float rstd = rsqrtf(var + 1e-6f);
            float xh0 = d0*rstd, xh1 = d1*rstd;
            float t0 = sV[n*64 + lane]      - sK[n*64 + lane];
            float t1 = sV[n*64 + lane + 32] - sK[n*64 + lane + 32];
            float g0 = sGw[lane], g1 = sGw[lane + 32];
            float gho0 = (g0*xh0 + sGb[lane]      - t0) * g0;
            float gho1 = (g1*xh1 + sGb[lane + 32] - t1) * g1;
            float sg  = warpsum(gho0 + gho1);
            float sgx = warpsum(gho0*xh0 + gho1*xh1);
            float e = sEta[n];
            float inv = rstd * (1.0f/64) * e;
            sZ[n*64 + lane]      = (64.f*gho0 - sg - xh0*sgx) * inv;
            sZ[n*64 + lane + 32] = (64.f*gho1 - sg - xh1*sgx) * inv;
        }
        __syncthreads();

        for (int n = 0; n < 64; n++) {
            float z = sZ[n*64 + tx];
            const float* kr = &sK[n*64 + ty*16];
#pragma unroll
            for (int i = 0; i < 16; i++) accW[i] += kr[i] * z;
            if ((n >> 4) == ty) accB += z;
        }
        __syncthreads();
    }

#pragma unroll
    for (int i = 0; i < 16; i++) sW1[(ty*16 + i)*64 + tx] -= accW[i];
    sBred[ty*64 + tx] = accB;
    __syncthreads();
    if (ty == 0)
        sB1b[tx] = sB1[tx] - (sBred[tx] + sBred[64+tx] + sBred[128+tx] + sBred[192+tx]);
    __syncthreads();

    for (int c = 0; c < 16; c++) {
        int n0 = c * 64;
        for (int i = tid; i < 4096; i += 256) {
            int n = i >> 6, e = i & 63;
            sK[i] = qbase[(size_t)(n0+n)*rs + e];
        }
        __syncthreads();
        {
            float az[16];
#pragma unroll
            for (int i = 0; i < 16; i++) az[i] = sB1b[tx];
            for (int d = 0; d < 64; d++) {
                float w = sW1[d*64 + tx];
#pragma unroll
                for (int i = 0; i < 16; i++) az[i] += sK[(i*4 + ty)*64 + d] * w;
            }
#pragma unroll
            for (int i = 0; i < 16; i++) sZ[(i*4 + ty)*64 + tx] = az[i];
        }
        __syncthreads();
        for (int j = 0; j < 8; j++) {
            int n = warp + 8*j;
            float z0 = sZ[n*64 + lane], z1 = sZ[n*64 + lane + 32];
            float mu = warpsum(z0 + z1) * (1.0f/64);
            float d0 = z0 - mu, d1 = z1 - mu;
            float var = warpsum(d0*d0 + d1*d1) * (1.0f/64);
            float rstd = rsqrtf(var + 1e-6f);
            float o0 = sK[n*64 + lane]      + sGw[lane]     *d0*rstd + sGb[lane];
            float o1 = sK[n*64 + lane + 32] + sGw[lane + 32]*d1*rstd + sGb[lane + 32];
            size_t orow = ((size_t)(b*NN + n0 + n))*CC + h*HD;
            __half hh, hl;
            split2h(o0, hh, hl); attnhi[orow + lane]      = hh; attnlo[orow + lane]      = hl;
            split2h(o1, hh, hl); attnhi[orow + lane + 32] = hh; attnlo[orow + lane + 32] = hl;
        }
        __syncthreads();
    }
}

// ---------------- launch ----------------
extern "C" void kernel_launch(void* const* d_in, const int* in_sizes, int n_in,
                              void* d_out, int out_size) {
    const float* x      = (const float*)d_in[0];
    const float* qkv_w  = (const float*)d_in[1];
    const float* q_bias = (const float*)d_in[2];
    const float* v_bias = (const float*)d_in[3];
    const float* proj_w = (const float*)d_in[4];
    const float* proj_b = (const float*)d_in[5];
    const float* lr_w   = (const float*)d_in[6];
    const float* lr_b   = (const float*)d_in[7];
    const float* W1     = (const float*)d_in[8];
    const float* b1     = (const float*)d_in[9];
    const float* ttt_w  = (const float*)d_in[10];
    const float* ttt_b  = (const float*)d_in[11];
    const float* n1w    = (const float*)d_in[12];
    const float* n1b    = (const float*)d_in[13];
    const float* n2w    = (const float*)d_in[14];
    const float* n2b    = (const float*)d_in[15];
    const float* fc1_w  = (const float*)d_in[16];
    const float* fc1_b  = (const float*)d_in[17];
    const float* fc2_w  = (const float*)d_in[18];
    const float* fc2_b  = (const float*)d_in[19];
    float* out = (float*)d_out;

    float *qkvb, *etap, *x2, *qbias;
    __half *hhi, *hlo, *athi, *atlo, *achi, *aclo;
    __half *wq, *wp, *w1, *w2;
    cudaGetSymbolAddress((void**)&qkvb,  g_qkv);
    cudaGetSymbolAddress((void**)&etap,  g_eta);
    cudaGetSymbolAddress((void**)&x2,    g_x2);
    cudaGetSymbolAddress((void**)&qbias, g_qkvbias);
    cudaGetSymbolAddress((void**)&hhi,   g_hhi);
    cudaGetSymbolAddress((void**)&hlo,   g_hlo);
    cudaGetSymbolAddress((void**)&athi,  g_attnhi);
    cudaGetSymbolAddress((void**)&atlo,  g_attnlo);
    cudaGetSymbolAddress((void**)&achi,  g_acthi);
    cudaGetSymbolAddress((void**)&aclo,  g_actlo);
    cudaGetSymbolAddress((void**)&wq,    g_wq);
    cudaGetSymbolAddress((void**)&wp,    g_wp);
    cudaGetSymbolAddress((void**)&w1,    g_w1);
    cudaGetSymbolAddress((void**)&w2,    g_w2);

    const int TTT_SMEM = (16384 + 64*5 + 256) * 4;
    cudaFuncSetAttribute(ttt_kernel, cudaFuncAttributeMaxDynamicSharedMemorySize, TTT_SMEM);
    cudaFuncSetAttribute(gemm_mma<0>, cudaFuncAttributeMaxDynamicSharedMemorySize, GEMM_SMEM);
    cudaFuncSetAttribute(gemm_mma<1>, cudaFuncAttributeMaxDynamicSharedMemorySize, GEMM_SMEM);
    cudaFuncSetAttribute(gemm_mma<2>, cudaFuncAttributeMaxDynamicSharedMemorySize, GEMM_SMEM);

    // merged weight conversion (fp32 -> fp16 single plane)
    const int WTOT = WQ_N + WP_N + W1_N + W2_N;
    convert_w<<<(WTOT + 255)/256, 256>>>(qkv_w, proj_w, fc1_w, fc2_w, wq, wp, w1, w2);
    qkvbias_kernel<<<(3*CC + 255)/256, 256>>>(q_bias, v_bias, qbias);

    // LN1 + eta
    ln_kernel<<<ROWS, 256>>>(x, n1w, n1b, lr_w, lr_b, hhi, hlo, etap);
    // qkv = h @ qkv_w^T + qkvbias  (fp32 out for TTT)
    gemm_mma<0><<<dim3(3*CC/BN, ROWS/BM), GTHREADS, GEMM_SMEM>>>(
        hhi, hlo, wq, qbias, nullptr, qkvb, nullptr, nullptr, ROWS, 3*CC, CC);
    // TTT attention
    ttt_kernel<<<BB*NH, 256, TTT_SMEM>>>(qkvb, etap, W1, b1, ttt_w, ttt_b, athi, atlo);
    // x2 = x + attn @ proj_w^T + proj_b
    gemm_mma<1><<<dim3(CC/BN, ROWS/BM), GTHREADS, GEMM_SMEM>>>(
        athi, atlo, wp, proj_b, x, x2, nullptr, nullptr, ROWS, CC, CC);
    // LN2
    ln_kernel<<<ROWS, 256>>>(x2, n2w, n2b, nullptr, nullptr, hhi, hlo, nullptr);
    // act = gelu(h2 @ fc1_w^T + fc1_b), split fp16 planes
    gemm_mma<2><<<dim3(4*CC/BN, ROWS/BM), GTHREADS, GEMM_SMEM>>>(
        hhi, hlo, w1, fc1_b, nullptr, nullptr, achi, aclo, ROWS, 4*CC, CC);
    // out = x2 + act @ fc2_w^T + fc2_b
    gemm_mma<1><<<dim3(CC/BN, ROWS/BM), GTHREADS, GEMM_SMEM>>>(
        achi, aclo, w2, fc2_b, x2, out, nullptr, nullptr, ROWS, CC, 4*CC);
}

// round 9
// speedup vs baseline: 2.1808x; 1.4479x over previous
#include <cuda_runtime.h>
#include <cuda_fp16.h>
#include <math.h>
#include <stdint.h>

#define BB 16
#define NN 1024
#define CC 768
#define NH 12
#define HD 64
#define ROWS (BB*NN)        // 16384

// GEMM tiling (mma.sync + cp.async path)
#define BM 128
#define BN 128
#define BK 32               // k elements per chunk
#define PITCH 40            // smem row pitch (fp16): 80B rows, 16B-aligned, conflict-free
#define NSTAGE 3
#define PLANE_ELEMS (128*PITCH)                 // 5120
#define GEMM_SMEM (NSTAGE*2*PLANE_ELEMS*2)      // 61440 B -> 2+ CTA/SM
#define GTHREADS 512

// ---------------- device scratch ----------------
__device__ float g_qkv[ROWS*3*CC];      // qkv projections fp32
__device__ float g_eta[BB*NH*NN];
__device__ float g_x2[ROWS*CC];         // x after proj residual (fp32)
__device__ float g_qkvbias[3*CC];
__device__ __align__(16) __half g_h[ROWS*CC];       // h / h2 fp16
__device__ __align__(16) __half g_attn[ROWS*CC];    // attn fp16
__device__ __align__(16) __half g_act[ROWS*4*CC];   // gelu(fc1) fp16
__device__ __align__(16) __half g_wq[3*CC*CC];      // weights fp16
__device__ __align__(16) __half g_wp[CC*CC];
__device__ __align__(16) __half g_w1[4*CC*CC];
__device__ __align__(16) __half g_w2[CC*4*CC];

// ---------------- helpers ----------------
__device__ __forceinline__ float warpsum(float v) {
#pragma unroll
    for (int o = 16; o > 0; o >>= 1) v += __shfl_xor_sync(0xffffffffu, v, o);
    return v;
}
__device__ __forceinline__ void mma16816(float* d, const uint32_t* a, const uint32_t* b) {
    asm volatile(
        "mma.sync.aligned.m16n8k16.row.col.f32.f16.f16.f32 "
        "{%0,%1,%2,%3}, {%4,%5,%6,%7}, {%8,%9}, {%0,%1,%2,%3};"
        : "+f"(d[0]), "+f"(d[1]), "+f"(d[2]), "+f"(d[3])
        : "r"(a[0]), "r"(a[1]), "r"(a[2]), "r"(a[3]), "r"(b[0]), "r"(b[1]));
}
__device__ __forceinline__ void cpasync16(uint32_t dst, const void* src) {
    asm volatile("cp.async.cg.shared.global [%0], [%1], 16;" :: "r"(dst), "l"(src));
}
__device__ __forceinline__ uint32_t smaddr(const void* p) {
    uint32_t a;
    asm("{ .reg .u64 t; cvta.to.shared.u64 t, %1; cvt.u32.u64 %0, t; }" : "=r"(a) : "l"(p));
    return a;
}
__device__ __forceinline__ void ldm_x4(uint32_t* r, uint32_t addr) {
    asm volatile("ldmatrix.sync.aligned.m8n8.x4.shared.b16 {%0,%1,%2,%3}, [%4];"
        : "=r"(r[0]), "=r"(r[1]), "=r"(r[2]), "=r"(r[3]) : "r"(addr));
}

// ---------------- small elementwise kernels ----------------
__global__ void qkvbias_kernel(const float* __restrict__ qb,
                               const float* __restrict__ vb,
                               float* __restrict__ out) {
    int i = blockIdx.x * blockDim.x + threadIdx.x;
    if (i < 3*CC) out[i] = (i < CC) ? qb[i] : (i < 2*CC ? 0.0f : vb[i - 2*CC]);
}
// one merged weight-conversion kernel: fp32 -> fp16
#define WQ_N (3*CC*CC)
#define WP_N (CC*CC)
#define W1_N (4*CC*CC)
#define W2_N (CC*4*CC)
__global__ void convert_w(const float* __restrict__ qkv_w, const float* __restrict__ proj_w,
                          const float* __restrict__ fc1_w, const float* __restrict__ fc2_w,
                          __half* __restrict__ wq, __half* __restrict__ wp,
                          __half* __restrict__ w1, __half* __restrict__ w2) {
    int i = blockIdx.x * blockDim.x + threadIdx.x;
    if (i < WQ_N) wq[i] = __float2half_rn(qkv_w[i]);
    else if (i < WQ_N + WP_N) { int j = i - WQ_N; wp[j] = __float2half_rn(proj_w[j]); }
    else if (i < WQ_N + WP_N + W1_N) { int j = i - WQ_N - WP_N; w1[j] = __float2half_rn(fc1_w[j]); }
    else if (i < WQ_N + WP_N + W1_N + W2_N) { int j = i - WQ_N - WP_N - W1_N; w2[j] = __float2half_rn(fc2_w[j]); }
}

// ---------------- LayerNorm (+ optional eta), fp16 out ----------------
__global__ void __launch_bounds__(256) ln_kernel(
    const float* __restrict__ x, const float* __restrict__ w, const float* __restrict__ bp,
    const float* __restrict__ lrw, const float* __restrict__ lrb,
    __half* __restrict__ hout, float* __restrict__ eta)
{
    __shared__ float redA[8], redB[8], pr[8*NH];
    int row = blockIdx.x;
    int tid = threadIdx.x, lane = tid & 31, warp = tid >> 5;
    const float* xr = x + (size_t)row * CC;
    float v0 = xr[tid], v1 = xr[tid+256], v2 = xr[tid+512];

    float s = warpsum(v0+v1+v2);
    if (lane == 0) redA[warp] = s;
    __syncthreads();
    float tot = 0.f;
#pragma unroll
    for (int i = 0; i < 8; i++) tot += redA[i];
    float mu = tot * (1.0f/CC);
    float d0 = v0-mu, d1 = v1-mu, d2 = v2-mu;
    float vsum = warpsum(d0*d0 + d1*d1 + d2*d2);
    if (lane == 0) redB[warp] = vsum;
    __syncthreads();
    float var = 0.f;
#pragma unroll
    for (int i = 0; i < 8; i++) var += redB[i];
    var *= (1.0f/CC);
    float rstd = rsqrtf(var + 1e-6f);

    float h0 = w[tid    ]*d0*rstd + bp[tid    ];
    float h1 = w[tid+256]*d1*rstd + bp[tid+256];
    float h2 = w[tid+512]*d2*rstd + bp[tid+512];
    size_t rb = (size_t)row * CC;
    hout[rb+tid]     = __float2half_rn(h0);
    hout[rb+tid+256] = __float2half_rn(h1);
    hout[rb+tid+512] = __float2half_rn(h2);

    if (eta) {
        float p[NH];
#pragma unroll
        for (int hh2 = 0; hh2 < NH; hh2++) {
            const float* lw = lrw + (size_t)hh2 * CC;
            p[hh2] = h0*lw[tid] + h1*lw[tid+256] + h2*lw[tid+512];
        }
#pragma unroll
        for (int hh2 = 0; hh2 < NH; hh2++) {
            float ps = warpsum(p[hh2]);
            if (lane == 0) pr[warp*NH + hh2] = ps;
        }
        __syncthreads();
        if (tid < NH) {
            float ss = 0.f;
#pragma unroll
            for (int wv = 0; wv < 8; wv++) ss += pr[wv*NH + tid];
            ss += lrb[tid];
            float sg = 1.0f / (1.0f + expf(-ss));
            int b = row >> 10, n = row & 1023;
            eta[((size_t)(b*NH + tid))*NN + n] = sg * (1.0f/HD);
        }
    }
}

// ---------------- cp.async + ldmatrix pipelined fp16 GEMM NT ----------------
// C[M,Nn] = epi(A @ B^T + bias); A, B single fp16 planes
// 512 threads, 16 warps in 4x4 grid, warp tile 32x32
// EPI: 0 = fp32 out; 1 = +Res fp32 out; 2 = gelu, fp16 out
template<int EPI>
__global__ void __launch_bounds__(GTHREADS, 2) gemm_mma(
    const __half* __restrict__ A, const __half* __restrict__ Bw,
    const float* __restrict__ bias, const float* __restrict__ Res,
    float* __restrict__ Cout, __half* __restrict__ Ch,
    int M, int Nn, int K)
{
    extern __shared__ __half smem[];
    uint32_t smbase = smaddr(smem);

    int tid = threadIdx.x;
    int lane = tid & 31, wid = tid >> 5;
    int wm = wid & 3, wn = wid >> 2;          // 4x4 warp grid, warp tile 32x32
    int g = lane >> 2, t4 = lane & 3;
    int bn = blockIdx.x * BN, bm = blockIdx.y * BM;
    const int nch = K / BK;

    const __half* planes[2] = { A + (size_t)bm*K, Bw + (size_t)bn*K };

    // cp.async coords: per plane, 128 rows x 4 segs of 16B = 512 tasks = 512 threads
    int lrow = tid >> 2, lseg = tid & 3;

    // ldmatrix lane row offsets (element units)
    int aRow = (wm*32 + (lane & 15))*PITCH + (lane >> 4)*8;
    int bRow = (wn*32 + (lane >> 4)*8 + (lane & 7))*PITCH + ((lane >> 3) & 1)*8;

    float acc[2][4][4];
#pragma unroll
    for (int i = 0; i < 2; i++)
#pragma unroll
        for (int j = 0; j < 4; j++)
#pragma unroll
            for (int k = 0; k < 4; k++) acc[i][j][k] = 0.f;

#define ISSUE(stage, c) do {                                                    \
        int kb = (c) * BK;                                                      \
        _Pragma("unroll")                                                       \
        for (int p = 0; p < 2; p++) {                                           \
            uint32_t dst = smbase +                                             \
                (((stage)*2 + p)*PLANE_ELEMS + lrow*PITCH + lseg*8)*2;          \
            cpasync16(dst, planes[p] + (size_t)lrow*K + kb + lseg*8);           \
        }                                                                       \
        asm volatile("cp.async.commit_group;" ::: "memory");                    \
    } while (0)

    ISSUE(0, 0);
    ISSUE(1, 1);

    for (int c = 0; c < nch; ++c) {
        int s = c % NSTAGE;
        asm volatile("cp.async.wait_group %0;" :: "n"(NSTAGE-2) : "memory");
        __syncthreads();
        int cn = c + NSTAGE - 1;
        if (cn < nch) ISSUE(cn % NSTAGE, cn);

        uint32_t pA = smbase + ((s*2 + 0)*PLANE_ELEMS)*2;
        uint32_t pB = smbase + ((s*2 + 1)*PLANE_ELEMS)*2;

#pragma unroll
        for (int ks = 0; ks < 2; ks++) {
            int kof = ks*16;
            uint32_t ah[2][4], bh[4][2];
#pragma unroll
            for (int mb = 0; mb < 2; mb++)
                ldm_x4(ah[mb], pA + (aRow + mb*16*PITCH + kof)*2);
#pragma unroll
            for (int p = 0; p < 2; p++) {
                uint32_t r[4];
                ldm_x4(r, pB + (bRow + p*16*PITCH + kof)*2);
                bh[2*p][0] = r[0]; bh[2*p][1] = r[1]; bh[2*p+1][0] = r[2]; bh[2*p+1][1] = r[3];
            }
#pragma unroll
            for (int mt = 0; mt < 2; mt++)
#pragma unroll
                for (int nt = 0; nt < 4; nt++) mma16816(acc[mt][nt], ah[mt], bh[nt]);
        }
    }
#undef ISSUE

    // epilogue: direct register -> global
#pragma unroll
    for (int mt = 0; mt < 2; mt++) {
#pragma unroll
        for (int nt = 0; nt < 4; nt++) {
            int r0 = bm + wm*32 + mt*16 + g;
            int c0 = bn + wn*32 + nt*8 + t4*2;
            float b0 = bias[c0], b1 = bias[c0+1];
#pragma unroll
            for (int half = 0; half < 2; half++) {
                int r = r0 + half*8;
                size_t gi = (size_t)r * Nn + c0;
                float v0 = acc[mt][nt][half*2]     + b0;
                float v1 = acc[mt][nt][half*2 + 1] + b1;
                if (EPI == 1) { v0 += Res[gi]; v1 += Res[gi+1]; }
                if (EPI == 2) {
                    v0 = 0.5f*v0*(1.0f + erff(v0*0.70710678118654752f));
                    v1 = 0.5f*v1*(1.0f + erff(v1*0.70710678118654752f));
                    Ch[gi]   = __float2half_rn(v0);
                    Ch[gi+1] = __float2half_rn(v1);
                } else {
                    Cout[gi]   = v0;
                    Cout[gi+1] = v1;
                }
            }
        }
    }
}

// ---------------- TTT kernel: one block per (b,h) ----------------
__global__ void __launch_bounds__(256) ttt_kernel(
    const float* __restrict__ qkv, const float* __restrict__ eta,
    const float* __restrict__ W1g, const float* __restrict__ b1g,
    const float* __restrict__ tttw, const float* __restrict__ tttb,
    __half* __restrict__ attn)
{
    extern __shared__ float sm[];
    float* sW1  = sm;            // 4096 (becomes W1_bar)
    float* sK   = sm + 4096;
    float* sV   = sm + 8192;
    float* sZ   = sm + 12288;
    float* sEta = sm + 16384;    // 64
    float* sGw  = sEta + 64;
    float* sGb  = sGw + 64;
    float* sB1  = sGb + 64;
    float* sB1b = sB1 + 64;
    float* sBred= sB1b + 64;     // 256

    int bh = blockIdx.x;
    int b = bh / NH, h = bh % NH;
    int tid = threadIdx.x, tx = tid & 63, ty = tid >> 6;
    int lane = tid & 31, warp = tid >> 5;

    for (int i = tid; i < 4096; i += 256) sW1[i] = W1g[h*4096 + i];
    if (tid < 64) {
        sGw[tid] = tttw[h*64 + tid];
        sGb[tid] = tttb[h*64 + tid];
        sB1[tid] = b1g[h*64 + tid];
    }
    __syncthreads();

    const size_t rs = 3*CC;
    const float* qbase = qkv + (size_t)b*NN*rs + 0*CC + h*HD;
    const float* kbase = qkv + (size_t)b*NN*rs + 1*CC + h*HD;
    const float* vbase = qkv + (size_t)b*NN*rs + 2*CC + h*HD;

    float accW[16];
#pragma unroll
    for (int i = 0; i < 16; i++) accW[i] = 0.f;
    float accB = 0.f;

    for (int c = 0; c < 16; c++) {
        int n0 = c * 64;
        for (int i = tid; i < 4096; i += 256) {
            int n = i >> 6, e = i & 63;
            sK[i] = kbase[(size_t)(n0+n)*rs + e];
            sV[i] = vbase[(size_t)(n0+n)*rs + e];
        }
        if (tid < 64) sEta[tid] = eta[(size_t)bh*NN + n0 + tid];
        __syncthreads();

        {
            float az[16];
#pragma unroll
            for (int i = 0; i < 16; i++) az[i] = sB1[tx];
            for (int d = 0; d < 64; d++) {
                float w = sW1[d*64 + tx];
#pragma unroll
                for (int i = 0; i < 16; i++) az[i] += sK[(i*4 + ty)*64 + d] * w;
            }
#pragma unroll
            for (int i = 0; i < 16; i++) sZ[(i*4 + ty)*64 + tx] = az[i];
        }
        __syncthreads();

        for (int j = 0; j < 8; j++) {
            int n = warp + 8*j;
            float z0 = sZ[n*64 + lane], z1 = sZ[n*64 + lane + 32];
            float mu = warpsum(z0 + z1) * (1.0f/64);
            float d0 = z0 - mu, d1 = z1 - mu;
            float var = warpsum(d0*d0 + d1*d1) * (1.0f/64);
            float rstd = rsqrtf(var + 1e-6f);
            float xh0 = d0*rstd, xh1 = d1*rstd;
            float t0 = sV[n*64 + lane]      - sK[n*64 + lane];
            float t1 = sV[n*64 + lane + 32] - sK[n*64 + lane + 32];
            float g0 = sGw[lane], g1 = sGw[lane + 32];
            float gho0 = (g0*xh0 + sGb[lane]      - t0) * g0;
            float gho1 = (g1*xh1 + sGb[lane + 32] - t1) * g1;
            float sg  = warpsum(gho0 + gho1);
            float sgx = warpsum(gho0*xh0 + gho1*xh1);
            float e = sEta[n];
            float inv = rstd * (1.0f/64) * e;
            sZ[n*64 + lane]      = (64.f*gho0 - sg - xh0*sgx) * inv;
            sZ[n*64 + lane + 32] = (64.f*gho1 - sg - xh1*sgx) * inv;
        }
        __syncthreads();

        for (int n = 0; n < 64; n++) {
            float z = sZ[n*64 + tx];
            const float* kr = &sK[n*64 + ty*16];
#pragma unroll
            for (int i = 0; i < 16; i++) accW[i] += kr[i] * z;
            if ((n >> 4) == ty) accB += z;
        }
        __syncthreads();
    }

#pragma unroll
    for (int i = 0; i < 16; i++) sW1[(ty*16 + i)*64 + tx] -= accW[i];
    sBred[ty*64 + tx] = accB;
    __syncthreads();
    if (ty == 0)
        sB1b[tx] = sB1[tx] - (sBred[tx] + sBred[64+tx] + sBred[128+tx] + sBred[192+tx]);
    __syncthreads();

    for (int c = 0; c < 16; c++) {
        int n0 = c * 64;
        for (int i = tid; i < 4096; i += 256) {
            int n = i >> 6, e = i & 63;
            sK[i] = qbase[(size_t)(n0+n)*rs + e];
        }
        __syncthreads();
        {
            float az[16];
#pragma unroll
            for (int i = 0; i < 16; i++) az[i] = sB1b[tx];
            for (int d = 0; d < 64; d++) {
                float w = sW1[d*64 + tx];
#pragma unroll
                for (int i = 0; i < 16; i++) az[i] += sK[(i*4 + ty)*64 + d] * w;
            }
#pragma unroll
            for (int i = 0; i < 16; i++) sZ[(i*4 + ty)*64 + tx] = az[i];
        }
        __syncthreads();
        for (int j = 0; j < 8; j++) {
            int n = warp + 8*j;
            float z0 = sZ[n*64 + lane], z1 = sZ[n*64 + lane + 32];
            float mu = warpsum(z0 + z1) * (1.0f/64);
            float d0 = z0 - mu, d1 = z1 - mu;
            float var = warpsum(d0*d0 + d1*d1) * (1.0f/64);
            float rstd = rsqrtf(var + 1e-6f);
            float o0 = sK[n*64 + lane]      + sGw[lane]     *d0*rstd + sGb[lane];
            float o1 = sK[n*64 + lane + 32] + sGw[lane + 32]*d1*rstd + sGb[lane + 32];
            size_t orow = ((size_t)(b*NN + n0 + n))*CC + h*HD;
            attn[orow + lane]      = __float2half_rn(o0);
            attn[orow + lane + 32] = __float2half_rn(o1);
        }
        __syncthreads();
    }
}

// ---------------- launch ----------------
extern "C" void kernel_launch(void* const* d_in, const int* in_sizes, int n_in,
                              void* d_out, int out_size) {
    const float* x      = (const float*)d_in[0];
    const float* qkv_w  = (const float*)d_in[1];
    const float* q_bias = (const float*)d_in[2];
    const float* v_bias = (const float*)d_in[3];
    const float* proj_w = (const float*)d_in[4];
    const float* proj_b = (const float*)d_in[5];
    const float* lr_w   = (const float*)d_in[6];
    const float* lr_b   = (const float*)d_in[7];
    const float* W1     = (const float*)d_in[8];
    const float* b1     = (const float*)d_in[9];
    const float* ttt_w  = (const float*)d_in[10];
    const float* ttt_b  = (const float*)d_in[11];
    const float* n1w    = (const float*)d_in[12];
    const float* n1b    = (const float*)d_in[13];
    const float* n2w    = (const float*)d_in[14];
    const float* n2b    = (const float*)d_in[15];
    const float* fc1_w  = (const float*)d_in[16];
    const float* fc1_b  = (const float*)d_in[17];
    const float* fc2_w  = (const float*)d_in[18];
    const float* fc2_b  = (const float*)d_in[19];
    float* out = (float*)d_out;

    float *qkvb, *etap, *x2, *qbias;
    __half *hp, *attnp, *actp, *wq, *wp, *w1, *w2;
    cudaGetSymbolAddress((void**)&qkvb,  g_qkv);
    cudaGetSymbolAddress((void**)&etap,  g_eta);
    cudaGetSymbolAddress((void**)&x2,    g_x2);
    cudaGetSymbolAddress((void**)&qbias, g_qkvbias);
    cudaGetSymbolAddress((void**)&hp,    g_h);
    cudaGetSymbolAddress((void**)&attnp, g_attn);
    cudaGetSymbolAddress((void**)&actp,  g_act);
    cudaGetSymbolAddress((void**)&wq,    g_wq);
    cudaGetSymbolAddress((void**)&wp,    g_wp);
    cudaGetSymbolAddress((void**)&w1,    g_w1);
    cudaGetSymbolAddress((void**)&w2,    g_w2);

    const int TTT_SMEM = (16384 + 64*5 + 256) * 4;
    cudaFuncSetAttribute(ttt_kernel, cudaFuncAttributeMaxDynamicSharedMemorySize, TTT_SMEM);
    cudaFuncSetAttribute(gemm_mma<0>, cudaFuncAttributeMaxDynamicSharedMemorySize, GEMM_SMEM);
    cudaFuncSetAttribute(gemm_mma<1>, cudaFuncAttributeMaxDynamicSharedMemorySize, GEMM_SMEM);
    cudaFuncSetAttribute(gemm_mma<2>, cudaFuncAttributeMaxDynamicSharedMemorySize, GEMM_SMEM);

    // merged weight conversion (fp32 -> fp16)
    const int WTOT = WQ_N + WP_N + W1_N + W2_N;
    convert_w<<<(WTOT + 255)/256, 256>>>(qkv_w, proj_w, fc1_w, fc2_w, wq, wp, w1, w2);
    qkvbias_kernel<<<(3*CC + 255)/256, 256>>>(q_bias, v_bias, qbias);

    // LN1 + eta
    ln_kernel<<<ROWS, 256>>>(x, n1w, n1b, lr_w, lr_b, hp, etap);
    // qkv = h @ qkv_w^T + qkvbias  (fp32 out for TTT)
    gemm_mma<0><<<dim3(3*CC/BN, ROWS/BM), GTHREADS, GEMM_SMEM>>>(
        hp, wq, qbias, nullptr, qkvb, nullptr, ROWS, 3*CC, CC);
    // TTT attention
    ttt_kernel<<<BB*NH, 256, TTT_SMEM>>>(qkvb, etap, W1, b1, ttt_w, ttt_b, attnp);
    // x2 = x + attn @ proj_w^T + proj_b
    gemm_mma<1><<<dim3(CC/BN, ROWS/BM), GTHREADS, GEMM_SMEM>>>(
        attnp, wp, proj_b, x, x2, nullptr, ROWS, CC, CC);
    // LN2
    ln_kernel<<<ROWS, 256>>>(x2, n2w, n2b, nullptr, nullptr, hp, nullptr);
    // act = gelu(h2 @ fc1_w^T + fc1_b), fp16
    gemm_mma<2><<<dim3(4*CC/BN, ROWS/BM), GTHREADS, GEMM_SMEM>>>(
        hp, w1, fc1_b, nullptr, nullptr, actp, ROWS, 4*CC, CC);
    // out = x2 + act @ fc2_w^T + fc2_b
    gemm_mma<1><<<dim3(CC/BN, ROWS/BM), GTHREADS, GEMM_SMEM>>>(
        actp, w2, fc2_b, x2, out, nullptr, ROWS, CC, 4*CC);
}

// round 10
// speedup vs baseline: 2.2463x; 1.0300x over previous
#include <cuda_runtime.h>
#include <cuda_fp16.h>
#include <math.h>
#include <stdint.h>

#define BB 16
#define NN 1024
#define CC 768
#define NH 12
#define HD 64
#define ROWS (BB*NN)        // 16384

// GEMM tiling (mma.sync + cp.async path)
#define BM 128
#define BN2 256
#define BK 32               // k elements per chunk
#define PITCH 40            // smem row pitch (fp16): 80B rows, 16B-aligned, conflict-free
#define NSTAGE 3
#define PLANE_A (128*PITCH)                 // 5120
#define PLANE_B (256*PITCH)                 // 10240
#define STAGE_EL (PLANE_A + PLANE_B)        // 15360
#define GEMM_SMEM (NSTAGE*STAGE_EL*2)       // 92160 B
#define GTHREADS 512

// ---------------- device scratch ----------------
__device__ float g_qkv[ROWS*3*CC];      // qkv projections fp32
__device__ float g_eta[BB*NH*NN];
__device__ float g_x2[ROWS*CC];         // x after proj residual (fp32)
__device__ float g_qkvbias[3*CC];
__device__ __align__(16) __half g_h[ROWS*CC];       // h / h2 fp16
__device__ __align__(16) __half g_attn[ROWS*CC];    // attn fp16
__device__ __align__(16) __half g_act[ROWS*4*CC];   // gelu(fc1) fp16
__device__ __align__(16) __half g_wq[3*CC*CC];      // weights fp16
__device__ __align__(16) __half g_wp[CC*CC];
__device__ __align__(16) __half g_w1[4*CC*CC];
__device__ __align__(16) __half g_w2[CC*4*CC];

// ---------------- helpers ----------------
__device__ __forceinline__ float warpsum(float v) {
#pragma unroll
    for (int o = 16; o > 0; o >>= 1) v += __shfl_xor_sync(0xffffffffu, v, o);
    return v;
}
__device__ __forceinline__ void mma16816(float* d, const uint32_t* a, const uint32_t* b) {
    asm volatile(
        "mma.sync.aligned.m16n8k16.row.col.f32.f16.f16.f32 "
        "{%0,%1,%2,%3}, {%4,%5,%6,%7}, {%8,%9}, {%0,%1,%2,%3};"
        : "+f"(d[0]), "+f"(d[1]), "+f"(d[2]), "+f"(d[3])
        : "r"(a[0]), "r"(a[1]), "r"(a[2]), "r"(a[3]), "r"(b[0]), "r"(b[1]));
}
__device__ __forceinline__ void cpasync16(uint32_t dst, const void* src) {
    asm volatile("cp.async.cg.shared.global [%0], [%1], 16;" :: "r"(dst), "l"(src));
}
__device__ __forceinline__ uint32_t smaddr(const void* p) {
    uint32_t a;
    asm("{ .reg .u64 t; cvta.to.shared.u64 t, %1; cvt.u32.u64 %0, t; }" : "=r"(a) : "l"(p));
    return a;
}
__device__ __forceinline__ void ldm_x4(uint32_t* r, uint32_t addr) {
    asm volatile("ldmatrix.sync.aligned.m8n8.x4.shared.b16 {%0,%1,%2,%3}, [%4];"
        : "=r"(r[0]), "=r"(r[1]), "=r"(r[2]), "=r"(r[3]) : "r"(addr));
}

// ---------------- small elementwise kernels ----------------
__global__ void qkvbias_kernel(const float* __restrict__ qb,
                               const float* __restrict__ vb,
                               float* __restrict__ out) {
    int i = blockIdx.x * blockDim.x + threadIdx.x;
    if (i < 3*CC) out[i] = (i < CC) ? qb[i] : (i < 2*CC ? 0.0f : vb[i - 2*CC]);
}
#define WQ_N (3*CC*CC)
#define WP_N (CC*CC)
#define W1_N (4*CC*CC)
#define W2_N (CC*4*CC)
__global__ void convert_w(const float* __restrict__ qkv_w, const float* __restrict__ proj_w,
                          const float* __restrict__ fc1_w, const float* __restrict__ fc2_w,
                          __half* __restrict__ wq, __half* __restrict__ wp,
                          __half* __restrict__ w1, __half* __restrict__ w2) {
    int i = blockIdx.x * blockDim.x + threadIdx.x;
    if (i < WQ_N) wq[i] = __float2half_rn(qkv_w[i]);
    else if (i < WQ_N + WP_N) { int j = i - WQ_N; wp[j] = __float2half_rn(proj_w[j]); }
    else if (i < WQ_N + WP_N + W1_N) { int j = i - WQ_N - WP_N; w1[j] = __float2half_rn(fc1_w[j]); }
    else if (i < WQ_N + WP_N + W1_N + W2_N) { int j = i - WQ_N - WP_N - W1_N; w2[j] = __float2half_rn(fc2_w[j]); }
}

// ---------------- LayerNorm (+ optional eta), fp16 out ----------------
__global__ void __launch_bounds__(256) ln_kernel(
    const float* __restrict__ x, const float* __restrict__ w, const float* __restrict__ bp,
    const float* __restrict__ lrw, const float* __restrict__ lrb,
    __half* __restrict__ hout, float* __restrict__ eta)
{
    __shared__ float redA[8], redB[8], pr[8*NH];
    int row = blockIdx.x;
    int tid = threadIdx.x, lane = tid & 31, warp = tid >> 5;
    const float* xr = x + (size_t)row * CC;
    float v0 = xr[tid], v1 = xr[tid+256], v2 = xr[tid+512];

    float s = warpsum(v0+v1+v2);
    if (lane == 0) redA[warp] = s;
    __syncthreads();
    float tot = 0.f;
#pragma unroll
    for (int i = 0; i < 8; i++) tot += redA[i];
    float mu = tot * (1.0f/CC);
    float d0 = v0-mu, d1 = v1-mu, d2 = v2-mu;
    float vsum = warpsum(d0*d0 + d1*d1 + d2*d2);
    if (lane == 0) redB[warp] = vsum;
    __syncthreads();
    float var = 0.f;
#pragma unroll
    for (int i = 0; i < 8; i++) var += redB[i];
    var *= (1.0f/CC);
    float rstd = rsqrtf(var + 1e-6f);

    float h0 = w[tid    ]*d0*rstd + bp[tid    ];
    float h1 = w[tid+256]*d1*rstd + bp[tid+256];
    float h2 = w[tid+512]*d2*rstd + bp[tid+512];
    size_t rb = (size_t)row * CC;
    hout[rb+tid]     = __float2half_rn(h0);
    hout[rb+tid+256] = __float2half_rn(h1);
    hout[rb+tid+512] = __float2half_rn(h2);

    if (eta) {
        float p[NH];
#pragma unroll
        for (int hh2 = 0; hh2 < NH; hh2++) {
            const float* lw = lrw + (size_t)hh2 * CC;
            p[hh2] = h0*lw[tid] + h1*lw[tid+256] + h2*lw[tid+512];
        }
#pragma unroll
        for (int hh2 = 0; hh2 < NH; hh2++) {
            float ps = warpsum(p[hh2]);
            if (lane == 0) pr[warp*NH + hh2] = ps;
        }
        __syncthreads();
        if (tid < NH) {
            float ss = 0.f;
#pragma unroll
            for (int wv = 0; wv < 8; wv++) ss += pr[wv*NH + tid];
            ss += lrb[tid];
            float sg = 1.0f / (1.0f + expf(-ss));
            int b = row >> 10, n = row & 1023;
            eta[((size_t)(b*NH + tid))*NN + n] = sg * (1.0f/HD);
        }
    }
}

// ---------------- cp.async + ldmatrix pipelined fp16 GEMM NT ----------------
// block tile 128x256, 16 warps 4x4, warp tile 32x64
// EPI: 0 = fp32 out; 1 = +Res fp32 out; 2 = gelu, fp16 out
template<int EPI>
__global__ void __launch_bounds__(GTHREADS) gemm_mma(
    const __half* __restrict__ A, const __half* __restrict__ Bw,
    const float* __restrict__ bias, const float* __restrict__ Res,
    float* __restrict__ Cout, __half* __restrict__ Ch,
    int M, int Nn, int K)
{
    extern __shared__ __half smem[];
    uint32_t smbase = smaddr(smem);

    int tid = threadIdx.x;
    int lane = tid & 31, wid = tid >> 5;
    int wm = wid & 3, wn = wid >> 2;          // 4x4 warp grid, warp tile 32x64
    int g = lane >> 2, t4 = lane & 3;
    int bn = blockIdx.x * BN2, bm = blockIdx.y * BM;
    const int nch = K / BK;

    const __half* Ag = A  + (size_t)bm*K;
    const __half* Bg = Bw + (size_t)bn*K;

    // cp.async: A 512 segs (1/thread), B 1024 segs (2/thread)
    int arow = tid >> 2, aseg = tid & 3;

    // ldmatrix lane offsets (element units)
    int aRow = (wm*32 + (lane & 15))*PITCH + (lane >> 4)*8;
    int bRow = (wn*64 + (lane >> 4)*8 + (lane & 7))*PITCH + ((lane >> 3) & 1)*8;

    float acc[2][8][4];
#pragma unroll
    for (int i = 0; i < 2; i++)
#pragma unroll
        for (int j = 0; j < 8; j++)
#pragma unroll
            for (int k = 0; k < 4; k++) acc[i][j][k] = 0.f;

#define ISSUE(stage, c) do {                                                    \
        int kb = (c) * BK;                                                      \
        uint32_t sb = smbase + ((stage)*STAGE_EL)*2;                            \
        cpasync16(sb + (arow*PITCH + aseg*8)*2,                                 \
                  Ag + (size_t)arow*K + kb + aseg*8);                           \
        _Pragma("unroll")                                                       \
        for (int it = 0; it < 2; it++) {                                        \
            int u = tid + it*512;                                               \
            int br = u >> 2, bs = u & 3;                                        \
            cpasync16(sb + (PLANE_A + br*PITCH + bs*8)*2,                       \
                      Bg + (size_t)br*K + kb + bs*8);                           \
        }                                                                       \
        asm volatile("cp.async.commit_group;" ::: "memory");                    \
    } while (0)

    ISSUE(0, 0);
    ISSUE(1, 1);

    for (int c = 0; c < nch; ++c) {
        int s = c % NSTAGE;
        asm volatile("cp.async.wait_group %0;" :: "n"(NSTAGE-2) : "memory");
        __syncthreads();
        int cn = c + NSTAGE - 1;
        if (cn < nch) ISSUE(cn % NSTAGE, cn);

        uint32_t pA = smbase + (s*STAGE_EL)*2;
        uint32_t pB = smbase + (s*STAGE_EL + PLANE_A)*2;

#pragma unroll
        for (int ks = 0; ks < 2; ks++) {
            int kof = ks*16;
            uint32_t ah[2][4], bh[8][2];
#pragma unroll
            for (int mb = 0; mb < 2; mb++)
                ldm_x4(ah[mb], pA + (aRow + mb*16*PITCH + kof)*2);
#pragma unroll
            for (int p = 0; p < 4; p++) {
                uint32_t r[4];
                ldm_x4(r, pB + (bRow + p*16*PITCH + kof)*2);
                bh[2*p][0] = r[0]; bh[2*p][1] = r[1]; bh[2*p+1][0] = r[2]; bh[2*p+1][1] = r[3];
            }
#pragma unroll
            for (int mt = 0; mt < 2; mt++)
#pragma unroll
                for (int nt = 0; nt < 8; nt++) mma16816(acc[mt][nt], ah[mt], bh[nt]);
        }
    }
#undef ISSUE

    // epilogue
#pragma unroll
    for (int mt = 0; mt < 2; mt++) {
#pragma unroll
        for (int nt = 0; nt < 8; nt++) {
            int r0 = bm + wm*32 + mt*16 + g;
            int c0 = bn + wn*64 + nt*8 + t4*2;
            float b0 = bias[c0], b1 = bias[c0+1];
#pragma unroll
            for (int half = 0; half < 2; half++) {
                int r = r0 + half*8;
                size_t gi = (size_t)r * Nn + c0;
                float v0 = acc[mt][nt][half*2]     + b0;
                float v1 = acc[mt][nt][half*2 + 1] + b1;
                if (EPI == 1) { v0 += Res[gi]; v1 += Res[gi+1]; }
                if (EPI == 2) {
                    v0 = 0.5f*v0*(1.0f + erff(v0*0.70710678118654752f));
                    v1 = 0.5f*v1*(1.0f + erff(v1*0.70710678118654752f));
                    Ch[gi]   = __float2half_rn(v0);
                    Ch[gi+1] = __float2half_rn(v1);
                } else {
                    Cout[gi]   = v0;
                    Cout[gi+1] = v1;
                }
            }
        }
    }
}

// ---------------- TTT kernel: one block per (b,h), 4x4 register-tiled GEMMs ----------------
__global__ void __launch_bounds__(256) ttt_kernel(
    const float* __restrict__ qkv, const float* __restrict__ eta,
    const float* __restrict__ W1g, const float* __restrict__ b1g,
    const float* __restrict__ tttw, const float* __restrict__ tttb,
    __half* __restrict__ attn)
{
    extern __shared__ float sm[];
    float* sW1  = sm;            // 4096 (becomes W1_bar)
    float* sK   = sm + 4096;
    float* sV   = sm + 8192;
    float* sZ   = sm + 12288;
    float* sEta = sm + 16384;    // 64
    float* sGw  = sEta + 64;
    float* sGb  = sGw + 64;
    float* sB1  = sGb + 64;
    float* sB1b = sB1 + 64;

    int bh = blockIdx.x;
    int b = bh / NH, h = bh % NH;
    int tid = threadIdx.x;
    int lane = tid & 31, warp = tid >> 5;
    int tg = tid >> 4;           // 0..15 row-group (4 rows each)
    int tc = (tid & 15) * 4;     // col base (4 cols)

    for (int i = tid; i < 4096; i += 256) sW1[i] = W1g[h*4096 + i];
    if (tid < 64) {
        sGw[tid] = tttw[h*64 + tid];
        sGb[tid] = tttb[h*64 + tid];
        sB1[tid] = b1g[h*64 + tid];
    }
    __syncthreads();

    const size_t rs = 3*CC;
    const float* qbase = qkv + (size_t)b*NN*rs + 0*CC + h*HD;
    const float* kbase = qkv + (size_t)b*NN*rs + 1*CC + h*HD;
    const float* vbase = qkv + (size_t)b*NN*rs + 2*CC + h*HD;

    float accW[4][4];
#pragma unroll
    for (int i = 0; i < 4; i++)
#pragma unroll
        for (int j = 0; j < 4; j++) accW[i][j] = 0.f;
    float accB[4] = {0.f, 0.f, 0.f, 0.f};

    for (int c = 0; c < 16; c++) {
        int n0 = c * 64;
        for (int i = tid; i < 4096; i += 256) {
            int n = i >> 6, e = i & 63;
            sK[i] = kbase[(size_t)(n0+n)*rs + e];
            sV[i] = vbase[(size_t)(n0+n)*rs + e];
        }
        if (tid < 64) sEta[tid] = eta[(size_t)bh*NN + n0 + tid];
        __syncthreads();

        // Z1 = K @ W1 + b1   (4x4 register tile, float4 smem loads)
        {
            float az[4][4];
#pragma unroll
            for (int i = 0; i < 4; i++)
#pragma unroll
                for (int j = 0; j < 4; j++) az[i][j] = sB1[tc+j];
            for (int d = 0; d < 64; d += 4) {
                float4 k4[4], w4[4];
#pragma unroll
                for (int i = 0; i < 4; i++) k4[i] = *(const float4*)&sK[(tg*4+i)*64 + d];
#pragma unroll
                for (int dd = 0; dd < 4; dd++) w4[dd] = *(const float4*)&sW1[(d+dd)*64 + tc];
#pragma unroll
                for (int i = 0; i < 4; i++) {
                    const float* kk = (const float*)&k4[i];
#pragma unroll
                    for (int dd = 0; dd < 4; dd++) {
                        const float* ww = (const float*)&w4[dd];
#pragma unroll
                        for (int j = 0; j < 4; j++) az[i][j] += kk[dd] * ww[j];
                    }
                }
            }
#pragma unroll
            for (int i = 0; i < 4; i++)
#pragma unroll
                for (int j = 0; j < 4; j++) sZ[(tg*4+i)*64 + tc + j] = az[i][j];
        }
        __syncthreads();

        // fused LN-L2 backward -> eg (in place in sZ), row-per-warp
        for (int j = 0; j < 8; j++) {
            int n = warp + 8*j;
            float z0 = sZ[n*64 + lane], z1 = sZ[n*64 + lane + 32];
            float mu = warpsum(z0 + z1) * (1.0f/64);
            float d0 = z0 - mu, d1 = z1 - mu;
            float var = warpsum(d0*d0 + d1*d1) * (1.0f/64);
            float rstd = rsqrtf(var + 1e-6f);
            float xh0 = d0*rstd, xh1 = d1*rstd;
            float t0 = sV[n*64 + lane]      - sK[n*64 + lane];
            float t1 = sV[n*64 + lane + 32] - sK[n*64 + lane + 32];
            float g0 = sGw[lane], g1 = sGw[lane + 32];
            float gho0 = (g0*xh0 + sGb[lane]      - t0) * g0;
            float gho1 = (g1*xh1 + sGb[lane + 32] - t1) * g1;
            float sg  = warpsum(gho0 + gho1);
            float sgx = warpsum(gho0*xh0 + gho1*xh1);
            float e = sEta[n];
            float inv = rstd * (1.0f/64) * e;
            sZ[n*64 + lane]      = (64.f*gho0 - sg - xh0*sgx) * inv;
            sZ[n*64 + lane + 32] = (64.f*gho1 - sg - xh1*sgx) * inv;
        }
        __syncthreads();

        // accW[d][e] += K[n][d]*eg[n][e];  accB[e] += eg[n][e]  (float4 loads)
        for (int n = 0; n < 64; n++) {
            float4 k4 = *(const float4*)&sK[n*64 + tg*4];
            float4 e4 = *(const float4*)&sZ[n*64 + tc];
            const float* kk = (const float*)&k4;
            const float* ee = (const float*)&e4;
#pragma unroll
            for (int i = 0; i < 4; i++)
#pragma unroll
                for (int j = 0; j < 4; j++) accW[i][j] += kk[i] * ee[j];
            if (tg == 0) {
#pragma unroll
                for (int j = 0; j < 4; j++) accB[j] += ee[j];
            }
        }
        __syncthreads();
    }

    // W1_bar in place; b1_bar
#pragma unroll
    for (int i = 0; i < 4; i++)
#pragma unroll
        for (int j = 0; j < 4; j++) sW1[(tg*4+i)*64 + tc + j] -= accW[i][j];
    if (tg == 0) {
#pragma unroll
        for (int j = 0; j < 4; j++) sB1b[tc+j] = sB1[tc+j] - accB[j];
    }
    __syncthreads();

    // pass 2: Z = Q @ W1_bar + b1_bar ; out = q + LN(Z)
    for (int c = 0; c < 16; c++) {
        int n0 = c * 64;
        for (int i = tid; i < 4096; i += 256) {
            int n = i >> 6, e = i & 63;
            sK[i] = qbase[(size_t)(n0+n)*rs + e];
        }
        __syncthreads();
        {
            float az[4][4];
#pragma unroll
            for (int i = 0; i < 4; i++)
#pragma unroll
                for (int j = 0; j < 4; j++) az[i][j] = sB1b[tc+j];
            for (int d = 0; d < 64; d += 4) {
                float4 k4[4], w4[4];
#pragma unroll
                for (int i = 0; i < 4; i++) k4[i] = *(const float4*)&sK[(tg*4+i)*64 + d];
#pragma unroll
                for (int dd = 0; dd < 4; dd++) w4[dd] = *(const float4*)&sW1[(d+dd)*64 + tc];
#pragma unroll
                for (int i = 0; i < 4; i++) {
                    const float* kk = (const float*)&k4[i];
#pragma unroll
                    for (int dd = 0; dd < 4; dd++) {
                        const float* ww = (const float*)&w4[dd];
#pragma unroll
                        for (int j = 0; j < 4; j++) az[i][j] += kk[dd] * ww[j];
                    }
                }
            }
#pragma unroll
            for (int i = 0; i < 4; i++)
#pragma unroll
                for (int j = 0; j < 4; j++) sZ[(tg*4+i)*64 + tc + j] = az[i][j];
        }
        __syncthreads();
        for (int j = 0; j < 8; j++) {
            int n = warp + 8*j;
            float z0 = sZ[n*64 + lane], z1 = sZ[n*64 + lane + 32];
            float mu = warpsum(z0 + z1) * (1.0f/64);
            float d0 = z0 - mu, d1 = z1 - mu;
            float var = warpsum(d0*d0 + d1*d1) * (1.0f/64);
            float rstd = rsqrtf(var + 1e-6f);
            float o0 = sK[n*64 + lane]      + sGw[lane]     *d0*rstd + sGb[lane];
            float o1 = sK[n*64 + lane + 32] + sGw[lane + 32]*d1*rstd + sGb[lane + 32];
            size_t orow = ((size_t)(b*NN + n0 + n))*CC + h*HD;
            attn[orow + lane]      = __float2half_rn(o0);
            attn[orow + lane + 32] = __float2half_rn(o1);
        }
        __syncthreads();
    }
}

// ---------------- launch ----------------
extern "C" void kernel_launch(void* const* d_in, const int* in_sizes, int n_in,
                              void* d_out, int out_size) {
    const float* x      = (const float*)d_in[0];
    const float* qkv_w  = (const float*)d_in[1];
    const float* q_bias = (const float*)d_in[2];
    const float* v_bias = (const float*)d_in[3];
    const float* proj_w = (const float*)d_in[4];
    const float* proj_b = (const float*)d_in[5];
    const float* lr_w   = (const float*)d_in[6];
    const float* lr_b   = (const float*)d_in[7];
    const float* W1     = (const float*)d_in[8];
    const float* b1     = (const float*)d_in[9];
    const float* ttt_w  = (const float*)d_in[10];
    const float* ttt_b  = (const float*)d_in[11];
    const float* n1w    = (const float*)d_in[12];
    const float* n1b    = (const float*)d_in[13];
    const float* n2w    = (const float*)d_in[14];
    const float* n2b    = (const float*)d_in[15];
    const float* fc1_w  = (const float*)d_in[16];
    const float* fc1_b  = (const float*)d_in[17];
    const float* fc2_w  = (const float*)d_in[18];
    const float* fc2_b  = (const float*)d_in[19];
    float* out = (float*)d_out;

    float *qkvb, *etap, *x2, *qbias;
    __half *hp, *attnp, *actp, *wq, *wp, *w1, *w2;
    cudaGetSymbolAddress((void**)&qkvb,  g_qkv);
    cudaGetSymbolAddress((void**)&etap,  g_eta);
    cudaGetSymbolAddress((void**)&x2,    g_x2);
    cudaGetSymbolAddress((void**)&qbias, g_qkvbias);
    cudaGetSymbolAddress((void**)&hp,    g_h);
    cudaGetSymbolAddress((void**)&attnp, g_attn);
    cudaGetSymbolAddress((void**)&actp,  g_act);
    cudaGetSymbolAddress((void**)&wq,    g_wq);
    cudaGetSymbolAddress((void**)&wp,    g_wp);
    cudaGetSymbolAddress((void**)&w1,    g_w1);
    cudaGetSymbolAddress((void**)&w2,    g_w2);

    const int TTT_SMEM = (16384 + 64*5) * 4;
    cudaFuncSetAttribute(ttt_kernel, cudaFuncAttributeMaxDynamicSharedMemorySize, TTT_SMEM);
    cudaFuncSetAttribute(gemm_mma<0>, cudaFuncAttributeMaxDynamicSharedMemorySize, GEMM_SMEM);
    cudaFuncSetAttribute(gemm_mma<1>, cudaFuncAttributeMaxDynamicSharedMemorySize, GEMM_SMEM);
    cudaFuncSetAttribute(gemm_mma<2>, cudaFuncAttributeMaxDynamicSharedMemorySize, GEMM_SMEM);

    // merged weight conversion (fp32 -> fp16)
    const int WTOT = WQ_N + WP_N + W1_N + W2_N;
    convert_w<<<(WTOT + 255)/256, 256>>>(qkv_w, proj_w, fc1_w, fc2_w, wq, wp, w1, w2);
    qkvbias_kernel<<<(3*CC + 255)/256, 256>>>(q_bias, v_bias, qbias);

    // LN1 + eta
    ln_kernel<<<ROWS, 256>>>(x, n1w, n1b, lr_w, lr_b, hp, etap);
    // qkv = h @ qkv_w^T + qkvbias  (fp32 out for TTT)
    gemm_mma<0><<<dim3(3*CC/BN2, ROWS/BM), GTHREADS, GEMM_SMEM>>>(
        hp, wq, qbias, nullptr, qkvb, nullptr, ROWS, 3*CC, CC);
    // TTT attention
    ttt_kernel<<<BB*NH, 256, TTT_SMEM>>>(qkvb, etap, W1, b1, ttt_w, ttt_b, attnp);
    // x2 = x + attn @ proj_w^T + proj_b
    gemm_mma<1><<<dim3(CC/BN2, ROWS/BM), GTHREADS, GEMM_SMEM>>>(
        attnp, wp, proj_b, x, x2, nullptr, ROWS, CC, CC);
    // LN2
    ln_kernel<<<ROWS, 256>>>(x2, n2w, n2b, nullptr, nullptr, hp, nullptr);
    // act = gelu(h2 @ fc1_w^T + fc1_b), fp16
    gemm_mma<2><<<dim3(4*CC/BN2, ROWS/BM), GTHREADS, GEMM_SMEM>>>(
        hp, w1, fc1_b, nullptr, nullptr, actp, ROWS, 4*CC, CC);
    // out = x2 + act @ fc2_w^T + fc2_b
    gemm_mma<1><<<dim3(CC/BN2, ROWS/BM), GTHREADS, GEMM_SMEM>>>(
        actp, w2, fc2_b, x2, out, nullptr, ROWS, CC, 4*CC);
}

// round 11
// speedup vs baseline: 2.4378x; 1.0853x over previous
#include <cuda_runtime.h>
#include <cuda_fp16.h>
#include <math.h>
#include <stdint.h>

#define BB 16
#define NN 1024
#define CC 768
#define NH 12
#define HD 64
#define ROWS (BB*NN)        // 16384

// GEMM tiling: block 128x128, BK=64, 2-stage cp.async, 16 warps 4x4 (warp 32x32)
#define BM 128
#define BN 128
#define BK 64
#define PITCH 72            // fp16 elems per smem row (144B): ldmatrix conflict-free, 16B aligned
#define PLANE_EL (128*PITCH)                 // 9216
#define STAGE_EL (2*PLANE_EL)                // 18432 (A + B)
#define GEMM_SMEM (2*STAGE_EL*2)             // 73728 B -> 2 CTAs/SM
#define GTHREADS 512

// ---------------- device scratch ----------------
__device__ float g_qkv[ROWS*3*CC];
__device__ float g_eta[BB*NH*NN];
__device__ float g_x2[ROWS*CC];
__device__ float g_qkvbias[3*CC];
__device__ __align__(16) __half g_h[ROWS*CC];
__device__ __align__(16) __half g_attn[ROWS*CC];
__device__ __align__(16) __half g_act[ROWS*4*CC];
__device__ __align__(16) __half g_wq[3*CC*CC];
__device__ __align__(16) __half g_wp[CC*CC];
__device__ __align__(16) __half g_w1[4*CC*CC];
__device__ __align__(16) __half g_w2[CC*4*CC];

// ---------------- helpers ----------------
__device__ __forceinline__ float warpsum(float v) {
#pragma unroll
    for (int o = 16; o > 0; o >>= 1) v += __shfl_xor_sync(0xffffffffu, v, o);
    return v;
}
__device__ __forceinline__ void mma16816(float* d, const uint32_t* a, const uint32_t* b) {
    asm volatile(
        "mma.sync.aligned.m16n8k16.row.col.f32.f16.f16.f32 "
        "{%0,%1,%2,%3}, {%4,%5,%6,%7}, {%8,%9}, {%0,%1,%2,%3};"
        : "+f"(d[0]), "+f"(d[1]), "+f"(d[2]), "+f"(d[3])
        : "r"(a[0]), "r"(a[1]), "r"(a[2]), "r"(a[3]), "r"(b[0]), "r"(b[1]));
}
__device__ __forceinline__ void cpasync16(uint32_t dst, const void* src) {
    asm volatile("cp.async.cg.shared.global [%0], [%1], 16;" :: "r"(dst), "l"(src));
}
__device__ __forceinline__ uint32_t smaddr(const void* p) {
    uint32_t a;
    asm("{ .reg .u64 t; cvta.to.shared.u64 t, %1; cvt.u32.u64 %0, t; }" : "=r"(a) : "l"(p));
    return a;
}
__device__ __forceinline__ void ldm_x4(uint32_t* r, uint32_t addr) {
    asm volatile("ldmatrix.sync.aligned.m8n8.x4.shared.b16 {%0,%1,%2,%3}, [%4];"
        : "=r"(r[0]), "=r"(r[1]), "=r"(r[2]), "=r"(r[3]) : "r"(addr));
}

// ---------------- small elementwise kernels ----------------
__global__ void qkvbias_kernel(const float* __restrict__ qb,
                               const float* __restrict__ vb,
                               float* __restrict__ out) {
    int i = blockIdx.x * blockDim.x + threadIdx.x;
    if (i < 3*CC) out[i] = (i < CC) ? qb[i] : (i < 2*CC ? 0.0f : vb[i - 2*CC]);
}
#define WQ_N (3*CC*CC)
#define WP_N (CC*CC)
#define W1_N (4*CC*CC)
#define W2_N (CC*4*CC)
__global__ void convert_w(const float* __restrict__ qkv_w, const float* __restrict__ proj_w,
                          const float* __restrict__ fc1_w, const float* __restrict__ fc2_w,
                          __half* __restrict__ wq, __half* __restrict__ wp,
                          __half* __restrict__ w1, __half* __restrict__ w2) {
    int i = blockIdx.x * blockDim.x + threadIdx.x;
    if (i < WQ_N) wq[i] = __float2half_rn(qkv_w[i]);
    else if (i < WQ_N + WP_N) { int j = i - WQ_N; wp[j] = __float2half_rn(proj_w[j]); }
    else if (i < WQ_N + WP_N + W1_N) { int j = i - WQ_N - WP_N; w1[j] = __float2half_rn(fc1_w[j]); }
    else if (i < WQ_N + WP_N + W1_N + W2_N) { int j = i - WQ_N - WP_N - W1_N; w2[j] = __float2half_rn(fc2_w[j]); }
}

// ---------------- LayerNorm, warp-per-row (+ optional eta), fp16 out ----------------
// 256 threads = 8 warps = 8 rows per block; grid = ROWS/8
__global__ void __launch_bounds__(256) ln_kernel(
    const float* __restrict__ x, const float* __restrict__ w, const float* __restrict__ bp,
    const float* __restrict__ lrw, const float* __restrict__ lrb,
    __half* __restrict__ hout, float* __restrict__ eta)
{
    int lane = threadIdx.x & 31, warp = threadIdx.x >> 5;
    int row = blockIdx.x * 8 + warp;
    const float4* xr = (const float4*)(x + (size_t)row * CC);

    float4 v[6];
    float s = 0.f;
#pragma unroll
    for (int j = 0; j < 6; j++) {
        v[j] = xr[j*32 + lane];
        s += v[j].x + v[j].y + v[j].z + v[j].w;
    }
    float mu = warpsum(s) * (1.0f/CC);
    float vs = 0.f;
#pragma unroll
    for (int j = 0; j < 6; j++) {
        v[j].x -= mu; v[j].y -= mu; v[j].z -= mu; v[j].w -= mu;
        vs += v[j].x*v[j].x + v[j].y*v[j].y + v[j].z*v[j].z + v[j].w*v[j].w;
    }
    float rstd = rsqrtf(warpsum(vs) * (1.0f/CC) + 1e-6f);

    const float4* wv = (const float4*)w;
    const float4* bv = (const float4*)bp;
    float h[24];
#pragma unroll
    for (int j = 0; j < 6; j++) {
        float4 ww = wv[j*32 + lane], bb = bv[j*32 + lane];
        h[j*4+0] = ww.x * v[j].x * rstd + bb.x;
        h[j*4+1] = ww.y * v[j].y * rstd + bb.y;
        h[j*4+2] = ww.z * v[j].z * rstd + bb.z;
        h[j*4+3] = ww.w * v[j].w * rstd + bb.w;
    }
    __half* hr = hout + (size_t)row * CC;
#pragma unroll
    for (int j = 0; j < 6; j++) {
        __half2 a = __floats2half2_rn(h[j*4+0], h[j*4+1]);
        __half2 b = __floats2half2_rn(h[j*4+2], h[j*4+3]);
        *(uint2*)&hr[(j*32 + lane)*4] = make_uint2(*(uint32_t*)&a, *(uint32_t*)&b);
    }

    if (eta) {
#pragma unroll
        for (int hh = 0; hh < NH; hh++) {
            const float4* lw = (const float4*)(lrw + (size_t)hh * CC);
            float p = 0.f;
#pragma unroll
            for (int j = 0; j < 6; j++) {
                float4 l4 = lw[j*32 + lane];
                p += h[j*4+0]*l4.x + h[j*4+1]*l4.y + h[j*4+2]*l4.z + h[j*4+3]*l4.w;
            }
            p = warpsum(p);
            if (lane == hh) {
                p += lrb[hh];
                float sg = 1.0f / (1.0f + expf(-p));
                int b = row >> 10, n = row & 1023;
                eta[((size_t)(b*NH + hh))*NN + n] = sg * (1.0f/HD);
            }
        }
    }
}

// ---------------- cp.async + ldmatrix 2-stage BK=64 fp16 GEMM NT ----------------
// block 128x128, 16 warps 4x4, warp tile 32x32
// EPI: 0 = fp32 out; 1 = +Res fp32 out; 2 = gelu, fp16 out
template<int EPI>
__global__ void __launch_bounds__(GTHREADS, 2) gemm_mma(
    const __half* __restrict__ A, const __half* __restrict__ Bw,
    const float* __restrict__ bias, const float* __restrict__ Res,
    float* __restrict__ Cout, __half* __restrict__ Ch,
    int M, int Nn, int K)
{
    extern __shared__ __half smem[];
    uint32_t smbase = smaddr(smem);

    int tid = threadIdx.x;
    int lane = tid & 31, wid = tid >> 5;
    int wm = wid & 3, wn = wid >> 2;          // 4x4 warp grid, warp tile 32x32
    int g = lane >> 2, t4 = lane & 3;
    int bn = blockIdx.x * BN, bm = blockIdx.y * BM;
    const int nch = K / BK;

    const __half* Ag = A  + (size_t)bm*K;
    const __half* Bg = Bw + (size_t)bn*K;

    // cp.async: per plane 128 rows x 8 segs of 16B = 1024 tasks -> 2/thread
    // ldmatrix lane offsets (element units)
    int aRow = (wm*32 + (lane & 15))*PITCH + (lane >> 4)*8;
    int bRow = (wn*32 + (lane >> 4)*8 + (lane & 7))*PITCH + ((lane >> 3) & 1)*8;

    float acc[2][4][4];
#pragma unroll
    for (int i = 0; i < 2; i++)
#pragma unroll
        for (int j = 0; j < 4; j++)
#pragma unroll
            for (int k = 0; k < 4; k++) acc[i][j][k] = 0.f;

#define ISSUE(stage, c) do {                                                    \
        int kb = (c) * BK;                                                      \
        uint32_t sb = smbase + ((stage)*STAGE_EL)*2;                            \
        _Pragma("unroll")                                                       \
        for (int it = 0; it < 2; it++) {                                        \
            int u = tid + it*512;                                               \
            int r0_ = u >> 3, s0_ = u & 7;                                      \
            cpasync16(sb + (r0_*PITCH + s0_*8)*2,                               \
                      Ag + (size_t)r0_*K + kb + s0_*8);                         \
            cpasync16(sb + (PLANE_EL + r0_*PITCH + s0_*8)*2,                    \
                      Bg + (size_t)r0_*K + kb + s0_*8);                         \
        }                                                                       \
        asm volatile("cp.async.commit_group;" ::: "memory");                    \
    } while (0)

    ISSUE(0, 0);

    for (int c = 0; c < nch; ++c) {
        int s = c & 1;
        asm volatile("cp.async.wait_group 0;" ::: "memory");
        __syncthreads();
        if (c + 1 < nch) ISSUE(s ^ 1, c + 1);

        uint32_t pA = smbase + (s*STAGE_EL)*2;
        uint32_t pB = smbase + (s*STAGE_EL + PLANE_EL)*2;

#pragma unroll
        for (int ks = 0; ks < 4; ks++) {
            int kof = ks*16;
            uint32_t ah[2][4], bh[4][2];
#pragma unroll
            for (int mb = 0; mb < 2; mb++)
                ldm_x4(ah[mb], pA + (aRow + mb*16*PITCH + kof)*2);
#pragma unroll
            for (int p = 0; p < 2; p++) {
                uint32_t r[4];
                ldm_x4(r, pB + (bRow + p*16*PITCH + kof)*2);
                bh[2*p][0] = r[0]; bh[2*p][1] = r[1]; bh[2*p+1][0] = r[2]; bh[2*p+1][1] = r[3];
            }
#pragma unroll
            for (int mt = 0; mt < 2; mt++)
#pragma unroll
                for (int nt = 0; nt < 4; nt++) mma16816(acc[mt][nt], ah[mt], bh[nt]);
        }
    }
#undef ISSUE

    // epilogue
#pragma unroll
    for (int mt = 0; mt < 2; mt++) {
#pragma unroll
        for (int nt = 0; nt < 4; nt++) {
            int r0 = bm + wm*32 + mt*16 + g;
            int c0 = bn + wn*32 + nt*8 + t4*2;
            float b0 = bias[c0], b1 = bias[c0+1];
#pragma unroll
            for (int half = 0; half < 2; half++) {
                int r = r0 + half*8;
                size_t gi = (size_t)r * Nn + c0;
                float v0 = acc[mt][nt][half*2]     + b0;
                float v1 = acc[mt][nt][half*2 + 1] + b1;
                if (EPI == 1) { v0 += Res[gi]; v1 += Res[gi+1]; }
                if (EPI == 2) {
                    v0 = 0.5f*v0*(1.0f + erff(v0*0.70710678118654752f));
                    v1 = 0.5f*v1*(1.0f + erff(v1*0.70710678118654752f));
                    Ch[gi]   = __float2half_rn(v0);
                    Ch[gi+1] = __float2half_rn(v1);
                } else {
                    Cout[gi]   = v0;
                    Cout[gi+1] = v1;
                }
            }
        }
    }
}

// ---------------- TTT kernel: one block per (b,h), 4x4 register-tiled GEMMs ----------------
__global__ void __launch_bounds__(256) ttt_kernel(
    const float* __restrict__ qkv, const float* __restrict__ eta,
    const float* __restrict__ W1g, const float* __restrict__ b1g,
    const float* __restrict__ tttw, const float* __restrict__ tttb,
    __half* __restrict__ attn)
{
    extern __shared__ float sm[];
    float* sW1  = sm;            // 4096 (becomes W1_bar)
    float* sK   = sm + 4096;
    float* sV   = sm + 8192;
    float* sZ   = sm + 12288;
    float* sEta = sm + 16384;    // 64
    float* sGw  = sEta + 64;
    float* sGb  = sGw + 64;
    float* sB1  = sGb + 64;
    float* sB1b = sB1 + 64;

    int bh = blockIdx.x;
    int b = bh / NH, h = bh % NH;
    int tid = threadIdx.x;
    int lane = tid & 31, warp = tid >> 5;
    int tg = tid >> 4;
    int tc = (tid & 15) * 4;

    for (int i = tid; i < 4096; i += 256) sW1[i] = W1g[h*4096 + i];
    if (tid < 64) {
        sGw[tid] = tttw[h*64 + tid];
        sGb[tid] = tttb[h*64 + tid];
        sB1[tid] = b1g[h*64 + tid];
    }
    __syncthreads();

    const size_t rs = 3*CC;
    const float* qbase = qkv + (size_t)b*NN*rs + 0*CC + h*HD;
    const float* kbase = qkv + (size_t)b*NN*rs + 1*CC + h*HD;
    const float* vbase = qkv + (size_t)b*NN*rs + 2*CC + h*HD;

    float accW[4][4];
#pragma unroll
    for (int i = 0; i < 4; i++)
#pragma unroll
        for (int j = 0; j < 4; j++) accW[i][j] = 0.f;
    float accB[4] = {0.f, 0.f, 0.f, 0.f};

    for (int c = 0; c < 16; c++) {
        int n0 = c * 64;
        for (int i = tid; i < 4096; i += 256) {
            int n = i >> 6, e = i & 63;
            sK[i] = kbase[(size_t)(n0+n)*rs + e];
            sV[i] = vbase[(size_t)(n0+n)*rs + e];
        }
        if (tid < 64) sEta[tid] = eta[(size_t)bh*NN + n0 + tid];
        __syncthreads();

        {
            float az[4][4];
#pragma unroll
            for (int i = 0; i < 4; i++)
#pragma unroll
                for (int j = 0; j < 4; j++) az[i][j] = sB1[tc+j];
            for (int d = 0; d < 64; d += 4) {
                float4 k4[4], w4[4];
#pragma unroll
                for (int i = 0; i < 4; i++) k4[i] = *(const float4*)&sK[(tg*4+i)*64 + d];
#pragma unroll
                for (int dd = 0; dd < 4; dd++) w4[dd] = *(const float4*)&sW1[(d+dd)*64 + tc];
#pragma unroll
                for (int i = 0; i < 4; i++) {
                    const float* kk = (const float*)&k4[i];
#pragma unroll
                    for (int dd = 0; dd < 4; dd++) {
                        const float* ww = (const float*)&w4[dd];
#pragma unroll
                        for (int j = 0; j < 4; j++) az[i][j] += kk[dd] * ww[j];
                    }
                }
            }
#pragma unroll
            for (int i = 0; i < 4; i++)
#pragma unroll
                for (int j = 0; j < 4; j++) sZ[(tg*4+i)*64 + tc + j] = az[i][j];
        }
        __syncthreads();

        for (int j = 0; j < 8; j++) {
            int n = warp + 8*j;
            float z0 = sZ[n*64 + lane], z1 = sZ[n*64 + lane + 32];
            float mu = warpsum(z0 + z1) * (1.0f/64);
            float d0 = z0 - mu, d1 = z1 - mu;
            float var = warpsum(d0*d0 + d1*d1) * (1.0f/64);
            float rstd = rsqrtf(var + 1e-6f);
            float xh0 = d0*rstd, xh1 = d1*rstd;
            float t0 = sV[n*64 + lane]      - sK[n*64 + lane];
            float t1 = sV[n*64 + lane + 32] - sK[n*64 + lane + 32];
            float g0 = sGw[lane], g1 = sGw[lane + 32];
            float gho0 = (g0*xh0 + sGb[lane]      - t0) * g0;
            float gho1 = (g1*xh1 + sGb[lane + 32] - t1) * g1;
            float sg  = warpsum(gho0 + gho1);
            float sgx = warpsum(gho0*xh0 + gho1*xh1);
            float e = sEta[n];
            float inv = rstd * (1.0f/64) * e;
            sZ[n*64 + lane]      = (64.f*gho0 - sg - xh0*sgx) * inv;
            sZ[n*64 + lane + 32] = (64.f*gho1 - sg - xh1*sgx) * inv;
        }
        __syncthreads();

        for (int n = 0; n < 64; n++) {
            float4 k4 = *(const float4*)&sK[n*64 + tg*4];
            float4 e4 = *(const float4*)&sZ[n*64 + tc];
            const float* kk = (const float*)&k4;
            const float* ee = (const float*)&e4;
#pragma unroll
            for (int i = 0; i < 4; i++)
#pragma unroll
                for (int j = 0; j < 4; j++) accW[i][j] += kk[i] * ee[j];
            if (tg == 0) {
#pragma unroll
                for (int j = 0; j < 4; j++) accB[j] += ee[j];
            }
        }
        __syncthreads();
    }

#pragma unroll
    for (int i = 0; i < 4; i++)
#pragma unroll
        for (int j = 0; j < 4; j++) sW1[(tg*4+i)*64 + tc + j] -= accW[i][j];
    if (tg == 0) {
#pragma unroll
        for (int j = 0; j < 4; j++) sB1b[tc+j] = sB1[tc+j] - accB[j];
    }
    __syncthreads();

    for (int c = 0; c < 16; c++) {
        int n0 = c * 64;
        for (int i = tid; i < 4096; i += 256) {
            int n = i >> 6, e = i & 63;
            sK[i] = qbase[(size_t)(n0+n)*rs + e];
        }
        __syncthreads();
        {
            float az[4][4];
#pragma unroll
            for (int i = 0; i < 4; i++)
#pragma unroll
                for (int j = 0; j < 4; j++) az[i][j] = sB1b[tc+j];
            for (int d = 0; d < 64; d += 4) {
                float4 k4[4], w4[4];
#pragma unroll
                for (int i = 0; i < 4; i++) k4[i] = *(const float4*)&sK[(tg*4+i)*64 + d];
#pragma unroll
                for (int dd = 0; dd < 4; dd++) w4[dd] = *(const float4*)&sW1[(d+dd)*64 + tc];
#pragma unroll
                for (int i = 0; i < 4; i++) {
                    const float* kk = (const float*)&k4[i];
#pragma unroll
                    for (int dd = 0; dd < 4; dd++) {
                        const float* ww = (const float*)&w4[dd];
#pragma unroll
                        for (int j = 0; j < 4; j++) az[i][j] += kk[dd] * ww[j];
                    }
                }
            }
#pragma unroll
            for (int i = 0; i < 4; i++)
#pragma unroll
                for (int j = 0; j < 4; j++) sZ[(tg*4+i)*64 + tc + j] = az[i][j];
        }
        __syncthreads();
        for (int j = 0; j < 8; j++) {
            int n = warp + 8*j;
            float z0 = sZ[n*64 + lane], z1 = sZ[n*64 + lane + 32];
            float mu = warpsum(z0 + z1) * (1.0f/64);
            float d0 = z0 - mu, d1 = z1 - mu;
            float var = warpsum(d0*d0 + d1*d1) * (1.0f/64);
            float rstd = rsqrtf(var + 1e-6f);
            float o0 = sK[n*64 + lane]      + sGw[lane]     *d0*rstd + sGb[lane];
            float o1 = sK[n*64 + lane + 32] + sGw[lane + 32]*d1*rstd + sGb[lane + 32];
            size_t orow = ((size_t)(b*NN + n0 + n))*CC + h*HD;
            attn[orow + lane]      = __float2half_rn(o0);
            attn[orow + lane + 32] = __float2half_rn(o1);
        }
        __syncthreads();
    }
}

// ---------------- launch ----------------
extern "C" void kernel_launch(void* const* d_in, const int* in_sizes, int n_in,
                              void* d_out, int out_size) {
    const float* x      = (const float*)d_in[0];
    const float* qkv_w  = (const float*)d_in[1];
    const float* q_bias = (const float*)d_in[2];
    const float* v_bias = (const float*)d_in[3];
    const float* proj_w = (const float*)d_in[4];
    const float* proj_b = (const float*)d_in[5];
    const float* lr_w   = (const float*)d_in[6];
    const float* lr_b   = (const float*)d_in[7];
    const float* W1     = (const float*)d_in[8];
    const float* b1     = (const float*)d_in[9];
    const float* ttt_w  = (const float*)d_in[10];
    const float* ttt_b  = (const float*)d_in[11];
    const float* n1w    = (const float*)d_in[12];
    const float* n1b    = (const float*)d_in[13];
    const float* n2w    = (const float*)d_in[14];
    const float* n2b    = (const float*)d_in[15];
    const float* fc1_w  = (const float*)d_in[16];
    const float* fc1_b  = (const float*)d_in[17];
    const float* fc2_w  = (const float*)d_in[18];
    const float* fc2_b  = (const float*)d_in[19];
    float* out = (float*)d_out;

    float *qkvb, *etap, *x2, *qbias;
    __half *hp, *attnp, *actp, *wq, *wp, *w1, *w2;
    cudaGetSymbolAddress((void**)&qkvb,  g_qkv);
    cudaGetSymbolAddress((void**)&etap,  g_eta);
    cudaGetSymbolAddress((void**)&x2,    g_x2);
    cudaGetSymbolAddress((void**)&qbias, g_qkvbias);
    cudaGetSymbolAddress((void**)&hp,    g_h);
    cudaGetSymbolAddress((void**)&attnp, g_attn);
    cudaGetSymbolAddress((void**)&actp,  g_act);
    cudaGetSymbolAddress((void**)&wq,    g_wq);
    cudaGetSymbolAddress((void**)&wp,    g_wp);
    cudaGetSymbolAddress((void**)&w1,    g_w1);
    cudaGetSymbolAddress((void**)&w2,    g_w2);

    const int TTT_SMEM = (16384 + 64*5) * 4;
    cudaFuncSetAttribute(ttt_kernel, cudaFuncAttributeMaxDynamicSharedMemorySize, TTT_SMEM);
    cudaFuncSetAttribute(gemm_mma<0>, cudaFuncAttributeMaxDynamicSharedMemorySize, GEMM_SMEM);
    cudaFuncSetAttribute(gemm_mma<1>, cudaFuncAttributeMaxDynamicSharedMemorySize, GEMM_SMEM);
    cudaFuncSetAttribute(gemm_mma<2>, cudaFuncAttributeMaxDynamicSharedMemorySize, GEMM_SMEM);

    const int WTOT = WQ_N + WP_N + W1_N + W2_N;
    convert_w<<<(WTOT + 255)/256, 256>>>(qkv_w, proj_w, fc1_w, fc2_w, wq, wp, w1, w2);
    qkvbias_kernel<<<(3*CC + 255)/256, 256>>>(q_bias, v_bias, qbias);

    // LN1 + eta (warp-per-row)
    ln_kernel<<<ROWS/8, 256>>>(x, n1w, n1b, lr_w, lr_b, hp, etap);
    // qkv = h @ qkv_w^T + qkvbias
    gemm_mma<0><<<dim3(3*CC/BN, ROWS/BM), GTHREADS, GEMM_SMEM>>>(
        hp, wq, qbias, nullptr, qkvb, nullptr, ROWS, 3*CC, CC);
    // TTT attention
    ttt_kernel<<<BB*NH, 256, TTT_SMEM>>>(qkvb, etap, W1, b1, ttt_w, ttt_b, attnp);
    // x2 = x + attn @ proj_w^T + proj_b
    gemm_mma<1><<<dim3(CC/BN, ROWS/BM), GTHREADS, GEMM_SMEM>>>(
        attnp, wp, proj_b, x, x2, nullptr, ROWS, CC, CC);
    // LN2
    ln_kernel<<<ROWS/8, 256>>>(x2, n2w, n2b, nullptr, nullptr, hp, nullptr);
    // act = gelu(h2 @ fc1_w^T + fc1_b)
    gemm_mma<2><<<dim3(4*CC/BN, ROWS/BM), GTHREADS, GEMM_SMEM>>>(
        hp, w1, fc1_b, nullptr, nullptr, actp, ROWS, 4*CC, CC);
    // out = x2 + act @ fc2_w^T + fc2_b
    gemm_mma<1><<<dim3(CC/BN, ROWS/BM), GTHREADS, GEMM_SMEM>>>(
        actp, w2, fc2_b, x2, out, nullptr, ROWS, CC, 4*CC);
}

// round 12
// speedup vs baseline: 2.8285x; 1.1603x over previous
#include <cuda_runtime.h>
#include <cuda_fp16.h>
#include <math.h>
#include <stdint.h>

#define BB 16
#define NN 1024
#define CC 768
#define NH 12
#define HD 64
#define ROWS (BB*NN)        // 16384

// GEMM tiling: block 128x128, BK=64, 2-stage cp.async, 8 warps 2x4 (warp 64x32)
#define BM 128
#define BN 128
#define BK 64
#define PITCH 72            // fp16 elems per smem row (144B): ldmatrix conflict-free, 16B aligned
#define PLANE_EL (128*PITCH)                 // 9216
#define STAGE_EL (2*PLANE_EL)                // 18432 (A + B)
#define GEMM_SMEM (2*STAGE_EL*2)             // 73728 B -> 2 CTAs/SM
#define GTHREADS 256

// ---------------- device scratch ----------------
__device__ float g_eta[BB*NH*NN];
__device__ float g_x2[ROWS*CC];
__device__ float g_qkvbias[3*CC];
__device__ __align__(16) __half g_qkv[ROWS*3*CC];   // qkv fp16
__device__ __align__(16) __half g_h[ROWS*CC];
__device__ __align__(16) __half g_attn[ROWS*CC];
__device__ __align__(16) __half g_act[ROWS*4*CC];
__device__ __align__(16) __half g_wq[3*CC*CC];
__device__ __align__(16) __half g_wp[CC*CC];
__device__ __align__(16) __half g_w1[4*CC*CC];
__device__ __align__(16) __half g_w2[CC*4*CC];

// ---------------- helpers ----------------
__device__ __forceinline__ float warpsum(float v) {
#pragma unroll
    for (int o = 16; o > 0; o >>= 1) v += __shfl_xor_sync(0xffffffffu, v, o);
    return v;
}
__device__ __forceinline__ void mma16816(float* d, const uint32_t* a, const uint32_t* b) {
    asm volatile(
        "mma.sync.aligned.m16n8k16.row.col.f32.f16.f16.f32 "
        "{%0,%1,%2,%3}, {%4,%5,%6,%7}, {%8,%9}, {%0,%1,%2,%3};"
        : "+f"(d[0]), "+f"(d[1]), "+f"(d[2]), "+f"(d[3])
        : "r"(a[0]), "r"(a[1]), "r"(a[2]), "r"(a[3]), "r"(b[0]), "r"(b[1]));
}
__device__ __forceinline__ void cpasync16(uint32_t dst, const void* src) {
    asm volatile("cp.async.cg.shared.global [%0], [%1], 16;" :: "r"(dst), "l"(src));
}
__device__ __forceinline__ uint32_t smaddr(const void* p) {
    uint32_t a;
    asm("{ .reg .u64 t; cvta.to.shared.u64 t, %1; cvt.u32.u64 %0, t; }" : "=r"(a) : "l"(p));
    return a;
}
__device__ __forceinline__ void ldm_x4(uint32_t* r, uint32_t addr) {
    asm volatile("ldmatrix.sync.aligned.m8n8.x4.shared.b16 {%0,%1,%2,%3}, [%4];"
        : "=r"(r[0]), "=r"(r[1]), "=r"(r[2]), "=r"(r[3]) : "r"(addr));
}

// ---------------- small elementwise kernels ----------------
__global__ void qkvbias_kernel(const float* __restrict__ qb,
                               const float* __restrict__ vb,
                               float* __restrict__ out) {
    int i = blockIdx.x * blockDim.x + threadIdx.x;
    if (i < 3*CC) out[i] = (i < CC) ? qb[i] : (i < 2*CC ? 0.0f : vb[i - 2*CC]);
}
#define WQ_N (3*CC*CC)
#define WP_N (CC*CC)
#define W1_N (4*CC*CC)
#define W2_N (CC*4*CC)
__global__ void convert_w(const float* __restrict__ qkv_w, const float* __restrict__ proj_w,
                          const float* __restrict__ fc1_w, const float* __restrict__ fc2_w,
                          __half* __restrict__ wq, __half* __restrict__ wp,
                          __half* __restrict__ w1, __half* __restrict__ w2) {
    int i = blockIdx.x * blockDim.x + threadIdx.x;
    if (i < WQ_N) wq[i] = __float2half_rn(qkv_w[i]);
    else if (i < WQ_N + WP_N) { int j = i - WQ_N; wp[j] = __float2half_rn(proj_w[j]); }
    else if (i < WQ_N + WP_N + W1_N) { int j = i - WQ_N - WP_N; w1[j] = __float2half_rn(fc1_w[j]); }
    else if (i < WQ_N + WP_N + W1_N + W2_N) { int j = i - WQ_N - WP_N - W1_N; w2[j] = __float2half_rn(fc2_w[j]); }
}

// ---------------- LayerNorm, warp-per-row (+ optional eta), fp16 out ----------------
__global__ void __launch_bounds__(256) ln_kernel(
    const float* __restrict__ x, const float* __restrict__ w, const float* __restrict__ bp,
    const float* __restrict__ lrw, const float* __restrict__ lrb,
    __half* __restrict__ hout, float* __restrict__ eta)
{
    int lane = threadIdx.x & 31, warp = threadIdx.x >> 5;
    int row = blockIdx.x * 8 + warp;
    const float4* xr = (const float4*)(x + (size_t)row * CC);

    float4 v[6];
    float s = 0.f;
#pragma unroll
    for (int j = 0; j < 6; j++) {
        v[j] = xr[j*32 + lane];
        s += v[j].x + v[j].y + v[j].z + v[j].w;
    }
    float mu = warpsum(s) * (1.0f/CC);
    float vs = 0.f;
#pragma unroll
    for (int j = 0; j < 6; j++) {
        v[j].x -= mu; v[j].y -= mu; v[j].z -= mu; v[j].w -= mu;
        vs += v[j].x*v[j].x + v[j].y*v[j].y + v[j].z*v[j].z + v[j].w*v[j].w;
    }
    float rstd = rsqrtf(warpsum(vs) * (1.0f/CC) + 1e-6f);

    const float4* wv = (const float4*)w;
    const float4* bv = (const float4*)bp;
    float h[24];
#pragma unroll
    for (int j = 0; j < 6; j++) {
        float4 ww = wv[j*32 + lane], bb = bv[j*32 + lane];
        h[j*4+0] = ww.x * v[j].x * rstd + bb.x;
        h[j*4+1] = ww.y * v[j].y * rstd + bb.y;
        h[j*4+2] = ww.z * v[j].z * rstd + bb.z;
        h[j*4+3] = ww.w * v[j].w * rstd + bb.w;
    }
    __half* hr = hout + (size_t)row * CC;
#pragma unroll
    for (int j = 0; j < 6; j++) {
        __half2 a = __floats2half2_rn(h[j*4+0], h[j*4+1]);
        __half2 b = __floats2half2_rn(h[j*4+2], h[j*4+3]);
        *(uint2*)&hr[(j*32 + lane)*4] = make_uint2(*(uint32_t*)&a, *(uint32_t*)&b);
    }

    if (eta) {
#pragma unroll
        for (int hh = 0; hh < NH; hh++) {
            const float4* lw = (const float4*)(lrw + (size_t)hh * CC);
            float p = 0.f;
#pragma unroll
            for (int j = 0; j < 6; j++) {
                float4 l4 = lw[j*32 + lane];
                p += h[j*4+0]*l4.x + h[j*4+1]*l4.y + h[j*4+2]*l4.z + h[j*4+3]*l4.w;
            }
            p = warpsum(p);
            if (lane == hh) {
                p += lrb[hh];
                float sg = 1.0f / (1.0f + expf(-p));
                int b = row >> 10, n = row & 1023;
                eta[((size_t)(b*NH + hh))*NN + n] = sg * (1.0f/HD);
            }
        }
    }
}

// ---------------- cp.async + ldmatrix 2-stage BK=64 fp16 GEMM NT ----------------
// block 128x128, 8 warps 2x4, warp tile 64x32
// EPI: 0 = fp32 out; 1 = +Res fp32 out; 2 = gelu fp16 out; 3 = plain fp16 out
template<int EPI>
__global__ void __launch_bounds__(GTHREADS, 2) gemm_mma(
    const __half* __restrict__ A, const __half* __restrict__ Bw,
    const float* __restrict__ bias, const float* __restrict__ Res,
    float* __restrict__ Cout, __half* __restrict__ Ch,
    int M, int Nn, int K)
{
    extern __shared__ __half smem[];
    uint32_t smbase = smaddr(smem);

    int tid = threadIdx.x;
    int lane = tid & 31, wid = tid >> 5;
    int wm = wid & 1, wn = wid >> 1;          // 2x4 warp grid, warp tile 64x32
    int g = lane >> 2, t4 = lane & 3;
    int bn = blockIdx.x * BN, bm = blockIdx.y * BM;
    const int nch = K / BK;

    const __half* Ag = A  + (size_t)bm*K;
    const __half* Bg = Bw + (size_t)bn*K;

    int aRow = (wm*64 + (lane & 15))*PITCH + (lane >> 4)*8;
    int bRow = (wn*32 + (lane >> 4)*8 + (lane & 7))*PITCH + ((lane >> 3) & 1)*8;

    float acc[4][4][4];
#pragma unroll
    for (int i = 0; i < 4; i++)
#pragma unroll
        for (int j = 0; j < 4; j++)
#pragma unroll
            for (int k = 0; k < 4; k++) acc[i][j][k] = 0.f;

#define ISSUE(stage, c) do {                                                    \
        int kb = (c) * BK;                                                      \
        uint32_t sb = smbase + ((stage)*STAGE_EL)*2;                            \
        _Pragma("unroll")                                                       \
        for (int it = 0; it < 4; it++) {                                        \
            int u = tid + it*256;                                               \
            int r0_ = u >> 3, s0_ = u & 7;                                      \
            cpasync16(sb + (r0_*PITCH + s0_*8)*2,                               \
                      Ag + (size_t)r0_*K + kb + s0_*8);                         \
            cpasync16(sb + (PLANE_EL + r0_*PITCH + s0_*8)*2,                    \
                      Bg + (size_t)r0_*K + kb + s0_*8);                         \
        }                                                                       \
        asm volatile("cp.async.commit_group;" ::: "memory");                    \
    } while (0)

    ISSUE(0, 0);

    for (int c = 0; c < nch; ++c) {
        int s = c & 1;
        asm volatile("cp.async.wait_group 0;" ::: "memory");
        __syncthreads();
        if (c + 1 < nch) ISSUE(s ^ 1, c + 1);

        uint32_t pA = smbase + (s*STAGE_EL)*2;
        uint32_t pB = smbase + (s*STAGE_EL + PLANE_EL)*2;

#pragma unroll
        for (int ks = 0; ks < 4; ks++) {
            int kof = ks*16;
            uint32_t ah[4][4], bh[4][2];
#pragma unroll
            for (int mb = 0; mb < 4; mb++)
                ldm_x4(ah[mb], pA + (aRow + mb*16*PITCH + kof)*2);
#pragma unroll
            for (int p = 0; p < 2; p++) {
                uint32_t r[4];
                ldm_x4(r, pB + (bRow + p*16*PITCH + kof)*2);
                bh[2*p][0] = r[0]; bh[2*p][1] = r[1]; bh[2*p+1][0] = r[2]; bh[2*p+1][1] = r[3];
            }
#pragma unroll
            for (int mt = 0; mt < 4; mt++)
#pragma unroll
                for (int nt = 0; nt < 4; nt++) mma16816(acc[mt][nt], ah[mt], bh[nt]);
        }
    }
#undef ISSUE

    // epilogue
#pragma unroll
    for (int mt = 0; mt < 4; mt++) {
#pragma unroll
        for (int nt = 0; nt < 4; nt++) {
            int r0 = bm + wm*64 + mt*16 + g;
            int c0 = bn + wn*32 + nt*8 + t4*2;
            float b0 = bias[c0], b1 = bias[c0+1];
#pragma unroll
            for (int half = 0; half < 2; half++) {
                int r = r0 + half*8;
                size_t gi = (size_t)r * Nn + c0;
                float v0 = acc[mt][nt][half*2]     + b0;
                float v1 = acc[mt][nt][half*2 + 1] + b1;
                if (EPI == 1) { v0 += Res[gi]; v1 += Res[gi+1]; }
                if (EPI == 2) {
                    v0 = 0.5f*v0*(1.0f + erff(v0*0.70710678118654752f));
                    v1 = 0.5f*v1*(1.0f + erff(v1*0.70710678118654752f));
                }
                if (EPI == 2 || EPI == 3) {
                    __half2 hv = __floats2half2_rn(v0, v1);
                    *(uint32_t*)&Ch[gi] = *(uint32_t*)&hv;
                } else {
                    Cout[gi]   = v0;
                    Cout[gi+1] = v1;
                }
            }
        }
    }
}

// ---------------- TTT kernel: one block per (b,h), 4x4 register-tiled GEMMs ----------------
__global__ void __launch_bounds__(256) ttt_kernel(
    const __half* __restrict__ qkv, const float* __restrict__ eta,
    const float* __restrict__ W1g, const float* __restrict__ b1g,
    const float* __restrict__ tttw, const float* __restrict__ tttb,
    __half* __restrict__ attn)
{
    extern __shared__ float sm[];
    float* sW1  = sm;            // 4096 (becomes W1_bar)
    float* sK   = sm + 4096;
    float* sV   = sm + 8192;
    float* sZ   = sm + 12288;
    float* sEta = sm + 16384;    // 64
    float* sGw  = sEta + 64;
    float* sGb  = sGw + 64;
    float* sB1  = sGb + 64;
    float* sB1b = sB1 + 64;

    int bh = blockIdx.x;
    int b = bh / NH, h = bh % NH;
    int tid = threadIdx.x;
    int lane = tid & 31, warp = tid >> 5;
    int tg = tid >> 4;
    int tc = (tid & 15) * 4;

    for (int i = tid; i < 4096; i += 256) sW1[i] = W1g[h*4096 + i];
    if (tid < 64) {
        sGw[tid] = tttw[h*64 + tid];
        sGb[tid] = tttb[h*64 + tid];
        sB1[tid] = b1g[h*64 + tid];
    }
    __syncthreads();

    const size_t rs = 3*CC;
    const __half* qbase = qkv + (size_t)b*NN*rs + 0*CC + h*HD;
    const __half* kbase = qkv + (size_t)b*NN*rs + 1*CC + h*HD;
    const __half* vbase = qkv + (size_t)b*NN*rs + 2*CC + h*HD;

    float accW[4][4];
#pragma unroll
    for (int i = 0; i < 4; i++)
#pragma unroll
        for (int j = 0; j < 4; j++) accW[i][j] = 0.f;
    float accB[4] = {0.f, 0.f, 0.f, 0.f};

    for (int c = 0; c < 16; c++) {
        int n0 = c * 64;
        // 4096 elems per tile, load as half2 pairs: 2048 tasks -> 8/thread
        for (int i = tid; i < 2048; i += 256) {
            int n = i >> 5, e2 = (i & 31) * 2;
            float2 kf = __half22float2(*(const __half2*)&kbase[(size_t)(n0+n)*rs + e2]);
            float2 vf = __half22float2(*(const __half2*)&vbase[(size_t)(n0+n)*rs + e2]);
            sK[n*64 + e2] = kf.x; sK[n*64 + e2 + 1] = kf.y;
            sV[n*64 + e2] = vf.x; sV[n*64 + e2 + 1] = vf.y;
        }
        if (tid < 64) sEta[tid] = eta[(size_t)bh*NN + n0 + tid];
        __syncthreads();

        {
            float az[4][4];
#pragma unroll
            for (int i = 0; i < 4; i++)
#pragma unroll
                for (int j = 0; j < 4; j++) az[i][j] = sB1[tc+j];
            for (int d = 0; d < 64; d += 4) {
                float4 k4[4], w4[4];
#pragma unroll
                for (int i = 0; i < 4; i++) k4[i] = *(const float4*)&sK[(tg*4+i)*64 + d];
#pragma unroll
                for (int dd = 0; dd < 4; dd++) w4[dd] = *(const float4*)&sW1[(d+dd)*64 + tc];
#pragma unroll
                for (int i = 0; i < 4; i++) {
                    const float* kk = (const float*)&k4[i];
#pragma unroll
                    for (int dd = 0; dd < 4; dd++) {
                        const float* ww = (const float*)&w4[dd];
#pragma unroll
                        for (int j = 0; j < 4; j++) az[i][j] += kk[dd] * ww[j];
                    }
                }
            }
#pragma unroll
            for (int i = 0; i < 4; i++)
#pragma unroll
                for (int j = 0; j < 4; j++) sZ[(tg*4+i)*64 + tc + j] = az[i][j];
        }
        __syncthreads();

        for (int j = 0; j < 8; j++) {
            int n = warp + 8*j;
            float z0 = sZ[n*64 + lane], z1 = sZ[n*64 + lane + 32];
            float mu = warpsum(z0 + z1) * (1.0f/64);
            float d0 = z0 - mu, d1 = z1 - mu;
            float var = warpsum(d0*d0 + d1*d1) * (1.0f/64);
            float rstd = rsqrtf(var + 1e-6f);
            float xh0 = d0*rstd, xh1 = d1*rstd;
            float t0 = sV[n*64 + lane]      - sK[n*64 + lane];
            float t1 = sV[n*64 + lane + 32] - sK[n*64 + lane + 32];
            float g0 = sGw[lane], g1 = sGw[lane + 32];
            float gho0 = (g0*xh0 + sGb[lane]      - t0) * g0;
            float gho1 = (g1*xh1 + sGb[lane + 32] - t1) * g1;
            float sg  = warpsum(gho0 + gho1);
            float sgx = warpsum(gho0*xh0 + gho1*xh1);
            float e = sEta[n];
            float inv = rstd * (1.0f/64) * e;
            sZ[n*64 + lane]      = (64.f*gho0 - sg - xh0*sgx) * inv;
            sZ[n*64 + lane + 32] = (64.f*gho1 - sg - xh1*sgx) * inv;
        }
        __syncthreads();

        for (int n = 0; n < 64; n++) {
            float4 k4 = *(const float4*)&sK[n*64 + tg*4];
            float4 e4 = *(const float4*)&sZ[n*64 + tc];
            const float* kk = (const float*)&k4;
            const float* ee = (const float*)&e4;
#pragma unroll
            for (int i = 0; i < 4; i++)
#pragma unroll
                for (int j = 0; j < 4; j++) accW[i][j] += kk[i] * ee[j];
            if (tg == 0) {
#pragma unroll
                for (int j = 0; j < 4; j++) accB[j] += ee[j];
            }
        }
        __syncthreads();
    }

#pragma unroll
    for (int i = 0; i < 4; i++)
#pragma unroll
        for (int j = 0; j < 4; j++) sW1[(tg*4+i)*64 + tc + j] -= accW[i][j];
    if (tg == 0) {
#pragma unroll
        for (int j = 0; j < 4; j++) sB1b[tc+j] = sB1[tc+j] - accB[j];
    }
    __syncthreads();

    for (int c = 0; c < 16; c++) {
        int n0 = c * 64;
        for (int i = tid; i < 2048; i += 256) {
            int n = i >> 5, e2 = (i & 31) * 2;
            float2 qf = __half22float2(*(const __half2*)&qbase[(size_t)(n0+n)*rs + e2]);
            sK[n*64 + e2] = qf.x; sK[n*64 + e2 + 1] = qf.y;
        }
        __syncthreads();
        {
            float az[4][4];
#pragma unroll
            for (int i = 0; i < 4; i++)
#pragma unroll
                for (int j = 0; j < 4; j++) az[i][j] = sB1b[tc+j];
            for (int d = 0; d < 64; d += 4) {
                float4 k4[4], w4[4];
#pragma unroll
                for (int i = 0; i < 4; i++) k4[i] = *(const float4*)&sK[(tg*4+i)*64 + d];
#pragma unroll
                for (int dd = 0; dd < 4; dd++) w4[dd] = *(const float4*)&sW1[(d+dd)*64 + tc];
#pragma unroll
                for (int i = 0; i < 4; i++) {
                    const float* kk = (const float*)&k4[i];
#pragma unroll
                    for (int dd = 0; dd < 4; dd++) {
                        const float* ww = (const float*)&w4[dd];
#pragma unroll
                        for (int j = 0; j < 4; j++) az[i][j] += kk[dd] * ww[j];
                    }
                }
            }
#pragma unroll
            for (int i = 0; i < 4; i++)
#pragma unroll
                for (int j = 0; j < 4; j++) sZ[(tg*4+i)*64 + tc + j] = az[i][j];
        }
        __syncthreads();
        for (int j = 0; j < 8; j++) {
            int n = warp + 8*j;
            float z0 = sZ[n*64 + lane], z1 = sZ[n*64 + lane + 32];
            float mu = warpsum(z0 + z1) * (1.0f/64);
            float d0 = z0 - mu, d1 = z1 - mu;
            float var = warpsum(d0*d0 + d1*d1) * (1.0f/64);
            float rstd = rsqrtf(var + 1e-6f);
            float o0 = sK[n*64 + lane]      + sGw[lane]     *d0*rstd + sGb[lane];
            float o1 = sK[n*64 + lane + 32] + sGw[lane + 32]*d1*rstd + sGb[lane + 32];
            size_t orow = ((size_t)(b*NN + n0 + n))*CC + h*HD;
            attn[orow + lane]      = __float2half_rn(o0);
            attn[orow + lane + 32] = __float2half_rn(o1);
        }
        __syncthreads();
    }
}

// ---------------- launch ----------------
extern "C" void kernel_launch(void* const* d_in, const int* in_sizes, int n_in,
                              void* d_out, int out_size) {
    const float* x      = (const float*)d_in[0];
    const float* qkv_w  = (const float*)d_in[1];
    const float* q_bias = (const float*)d_in[2];
    const float* v_bias = (const float*)d_in[3];
    const float* proj_w = (const float*)d_in[4];
    const float* proj_b = (const float*)d_in[5];
    const float* lr_w   = (const float*)d_in[6];
    const float* lr_b   = (const float*)d_in[7];
    const float* W1     = (const float*)d_in[8];
    const float* b1     = (const float*)d_in[9];
    const float* ttt_w  = (const float*)d_in[10];
    const float* ttt_b  = (const float*)d_in[11];
    const float* n1w    = (const float*)d_in[12];
    const float* n1b    = (const float*)d_in[13];
    const float* n2w    = (const float*)d_in[14];
    const float* n2b    = (const float*)d_in[15];
    const float* fc1_w  = (const float*)d_in[16];
    const float* fc1_b  = (const float*)d_in[17];
    const float* fc2_w  = (const float*)d_in[18];
    const float* fc2_b  = (const float*)d_in[19];
    float* out = (float*)d_out;

    float *etap, *x2, *qbias;
    __half *qkvp, *hp, *attnp, *actp, *wq, *wp, *w1, *w2;
    cudaGetSymbolAddress((void**)&qkvp,  g_qkv);
    cudaGetSymbolAddress((void**)&etap,  g_eta);
    cudaGetSymbolAddress((void**)&x2,    g_x2);
    cudaGetSymbolAddress((void**)&qbias, g_qkvbias);
    cudaGetSymbolAddress((void**)&hp,    g_h);
    cudaGetSymbolAddress((void**)&attnp, g_attn);
    cudaGetSymbolAddress((void**)&actp,  g_act);
    cudaGetSymbolAddress((void**)&wq,    g_wq);
    cudaGetSymbolAddress((void**)&wp,    g_wp);
    cudaGetSymbolAddress((void**)&w1,    g_w1);
    cudaGetSymbolAddress((void**)&w2,    g_w2);

    const int TTT_SMEM = (16384 + 64*5) * 4;
    cudaFuncSetAttribute(ttt_kernel, cudaFuncAttributeMaxDynamicSharedMemorySize, TTT_SMEM);
    cudaFuncSetAttribute(gemm_mma<1>, cudaFuncAttributeMaxDynamicSharedMemorySize, GEMM_SMEM);
    cudaFuncSetAttribute(gemm_mma<2>, cudaFuncAttributeMaxDynamicSharedMemorySize, GEMM_SMEM);
    cudaFuncSetAttribute(gemm_mma<3>, cudaFuncAttributeMaxDynamicSharedMemorySize, GEMM_SMEM);

    const int WTOT = WQ_N + WP_N + W1_N + W2_N;
    convert_w<<<(WTOT + 255)/256, 256>>>(qkv_w, proj_w, fc1_w, fc2_w, wq, wp, w1, w2);
    qkvbias_kernel<<<(3*CC + 255)/256, 256>>>(q_bias, v_bias, qbias);

    // LN1 + eta (warp-per-row)
    ln_kernel<<<ROWS/8, 256>>>(x, n1w, n1b, lr_w, lr_b, hp, etap);
    // qkv = h @ qkv_w^T + qkvbias  (fp16 out)
    gemm_mma<3><<<dim3(3*CC/BN, ROWS/BM), GTHREADS, GEMM_SMEM>>>(
        hp, wq, qbias, nullptr, nullptr, qkvp, ROWS, 3*CC, CC);
    // TTT attention
    ttt_kernel<<<BB*NH, 256, TTT_SMEM>>>(qkvp, etap, W1, b1, ttt_w, ttt_b, attnp);
    // x2 = x + attn @ proj_w^T + proj_b
    gemm_mma<1><<<dim3(CC/BN, ROWS/BM), GTHREADS, GEMM_SMEM>>>(
        attnp, wp, proj_b, x, x2, nullptr, ROWS, CC, CC);
    // LN2
    ln_kernel<<<ROWS/8, 256>>>(x2, n2w, n2b, nullptr, nullptr, hp, nullptr);
    // act = gelu(h2 @ fc1_w^T + fc1_b)
    gemm_mma<2><<<dim3(4*CC/BN, ROWS/BM), GTHREADS, GEMM_SMEM>>>(
        hp, w1, fc1_b, nullptr, nullptr, actp, ROWS, 4*CC, CC);
    // out = x2 + act @ fc2_w^T + fc2_b
    gemm_mma<1><<<dim3(CC/BN, ROWS/BM), GTHREADS, GEMM_SMEM>>>(
        actp, w2, fc2_b, x2, out, nullptr, ROWS, CC, 4*CC);
}